// round 10
// baseline (speedup 1.0000x reference)
#include <cuda_runtime.h>
#include <cuda_bf16.h>
#include <math.h>
#include <stdint.h>

// ---------------------------------------------------------------------------
// Problem constants (Qwen2Attention_11725260718470)
// ---------------------------------------------------------------------------
#define T_TOK   4096
#define HDIM    3584
#define NH      28
#define NKV     4
#define DHEAD   128
#define GROUP   7
#define BATCH   4
#define SEQ     1024
#define QKV_OUT 4608
#define NSLOTS  8192
#define SCALE_F 0.08838834764831845f
#define NEG_BIG (-1e30f)

// ---------------------------------------------------------------------------
// Device scratch
// ---------------------------------------------------------------------------
__device__ float g_qkv[(size_t)T_TOK * QKV_OUT];

__device__ __nv_bfloat16 g_hid_hi[(size_t)T_TOK * HDIM];
__device__ __nv_bfloat16 g_hid_lo[(size_t)T_TOK * HDIM];
__device__ __nv_bfloat16 g_wqkv_hi[(size_t)QKV_OUT * HDIM];
__device__ __nv_bfloat16 g_wqkv_lo[(size_t)QKV_OUT * HDIM];
__device__ __nv_bfloat16 g_wo_hi[(size_t)HDIM * HDIM];
__device__ __nv_bfloat16 g_wo_lo[(size_t)HDIM * HDIM];
__device__ __nv_bfloat16 g_ctx_hi[(size_t)T_TOK * HDIM];
__device__ __nv_bfloat16 g_ctx_lo[(size_t)T_TOK * HDIM];

// bf16 mirrors for attention (written by rope kernel)
__device__ __nv_bfloat16 g_qb [(size_t)T_TOK * NH * DHEAD];
__device__ __nv_bfloat16 g_kb [(size_t)T_TOK * NKV * DHEAD];
__device__ __nv_bfloat16 g_vhb[(size_t)T_TOK * NKV * DHEAD];
__device__ __nv_bfloat16 g_vlb[(size_t)T_TOK * NKV * DHEAD];

// ---------------------------------------------------------------------------
// Baseline-PTX helpers
// ---------------------------------------------------------------------------
__device__ __forceinline__ uint32_t smem_u32(const void* p) {
    uint32_t a;
    asm("{ .reg .u64 t; cvta.to.shared.u64 t, %1; cvt.u32.u64 %0, t; }"
        : "=r"(a) : "l"(p));
    return a;
}
__device__ __forceinline__ void cp_async16(uint32_t dst, const void* src) {
    asm volatile("cp.async.cg.shared.global [%0], [%1], 16;"
                 :: "r"(dst), "l"(src));
}
__device__ __forceinline__ void cp_commit() {
    asm volatile("cp.async.commit_group;");
}
__device__ __forceinline__ void ldmx4(uint32_t* r, uint32_t addr) {
    asm volatile("ldmatrix.sync.aligned.m8n8.x4.shared.b16 {%0,%1,%2,%3}, [%4];"
                 : "=r"(r[0]), "=r"(r[1]), "=r"(r[2]), "=r"(r[3]) : "r"(addr));
}
__device__ __forceinline__ void ldmx2(uint32_t* r, uint32_t addr) {
    asm volatile("ldmatrix.sync.aligned.m8n8.x2.shared.b16 {%0,%1}, [%2];"
                 : "=r"(r[0]), "=r"(r[1]) : "r"(addr));
}
__device__ __forceinline__ void ldmx2t(uint32_t* r, uint32_t addr) {
    asm volatile("ldmatrix.sync.aligned.m8n8.x2.trans.shared.b16 {%0,%1}, [%2];"
                 : "=r"(r[0]), "=r"(r[1]) : "r"(addr));
}
__device__ __forceinline__ void mma16816(float* c, const uint32_t* a, const uint32_t* b) {
    asm volatile(
        "mma.sync.aligned.m16n8k16.row.col.f32.bf16.bf16.f32 "
        "{%0,%1,%2,%3}, {%4,%5,%6,%7}, {%8,%9}, {%0,%1,%2,%3};"
        : "+f"(c[0]), "+f"(c[1]), "+f"(c[2]), "+f"(c[3])
        : "r"(a[0]), "r"(a[1]), "r"(a[2]), "r"(a[3]), "r"(b[0]), "r"(b[1]));
}

// ---------------------------------------------------------------------------
// Split fp32 -> bf16 hi/lo
// ---------------------------------------------------------------------------
__device__ __forceinline__ uint32_t pack_bf2(__nv_bfloat16 a, __nv_bfloat16 b) {
    return (uint32_t)__bfloat16_as_ushort(a) | ((uint32_t)__bfloat16_as_ushort(b) << 16);
}
__global__ void split_f32_bf16(const float4* __restrict__ x,
                               uint2* __restrict__ hi, uint2* __restrict__ lo, int n4) {
    int i = blockIdx.x * blockDim.x + threadIdx.x;
    if (i >= n4) return;
    float4 v = x[i];
    __nv_bfloat16 h0 = __float2bfloat16(v.x);
    __nv_bfloat16 h1 = __float2bfloat16(v.y);
    __nv_bfloat16 h2 = __float2bfloat16(v.z);
    __nv_bfloat16 h3 = __float2bfloat16(v.w);
    __nv_bfloat16 l0 = __float2bfloat16(v.x - __bfloat162float(h0));
    __nv_bfloat16 l1 = __float2bfloat16(v.y - __bfloat162float(h1));
    __nv_bfloat16 l2 = __float2bfloat16(v.z - __bfloat162float(h2));
    __nv_bfloat16 l3 = __float2bfloat16(v.w - __bfloat162float(h3));
    uint2 hv, lv;
    hv.x = pack_bf2(h0, h1); hv.y = pack_bf2(h2, h3);
    lv.x = pack_bf2(l0, l1); lv.y = pack_bf2(l2, l3);
    hi[i] = hv;
    lo[i] = lv;
}

// ---------------------------------------------------------------------------
// bf16x3 split-precision GEMM on mma.sync — 512 threads (16 warps, 4/SMSP),
// warp tile 32x32, 2-stage cp.async double buffer (R8 structure).
// ---------------------------------------------------------------------------
#define GBK        32
#define ROW_B      80
#define TILE_B     (128 * ROW_B)
#define STAGE_B    (4 * TILE_B)          // 40960
#define GSMEM_BYTES (2 * STAGE_B)        // 81920

__global__ __launch_bounds__(512, 1)
void gemm_bf16x3(const __nv_bfloat16* __restrict__ Ahi, const __nv_bfloat16* __restrict__ Alo,
                 const __nv_bfloat16* __restrict__ Bhi, const __nv_bfloat16* __restrict__ Blo,
                 const float* __restrict__ bias, float* __restrict__ C,
                 int M, int N, int K) {
    extern __shared__ char smem[];
    const uint32_t sbase = smem_u32(smem);

    const int tid  = threadIdx.x;
    const int wid  = tid >> 5;
    const int lane = tid & 31;
    const int bm = blockIdx.y * 128;
    const int bn = blockIdx.x * 128;
    const int warp_m = (wid >> 2) * 32;     // 0,32,64,96
    const int warp_n = (wid & 3) * 32;      // 0,32,64,96

    const __nv_bfloat16* gsrc[4] = {
        Ahi + (size_t)bm * K, Alo + (size_t)bm * K,
        Bhi + (size_t)bn * K, Blo + (size_t)bn * K };

    const int NS = K / GBK;

    // 512 threads: each thread loads exactly one 16B chunk per tile (4 tiles)
    auto load_stage = [&](int buf, int k0) {
        const uint32_t sb = sbase + buf * STAGE_B;
        const int row = tid >> 2;
        const int cc  = tid & 3;
        #pragma unroll
        for (int t = 0; t < 4; t++) {
            cp_async16(sb + t * TILE_B + row * ROW_B + cc * 16,
                       gsrc[t] + k0 + (size_t)row * K + cc * 8);
        }
        cp_commit();
    };

    float acc[2][4][4];
    #pragma unroll
    for (int mt = 0; mt < 2; mt++)
        #pragma unroll
        for (int nt = 0; nt < 4; nt++)
            #pragma unroll
            for (int j = 0; j < 4; j++) acc[mt][nt][j] = 0.f;

    load_stage(0, 0);

    const int a_row  = warp_m + ((lane >> 3) & 1) * 8 + (lane & 7);
    const int a_koff = ((lane >> 4) & 1) * 16;
    const int l2     = lane & 15;
    const int b_row  = warp_n + (l2 & 7);
    const int b_koff = ((l2 >> 3) & 1) * 16;

    for (int s = 0; s < NS; s++) {
        if (s + 1 < NS) {
            load_stage((s + 1) & 1, (s + 1) * GBK);
            asm volatile("cp.async.wait_group 1;");
        } else {
            asm volatile("cp.async.wait_group 0;");
        }
        __syncthreads();

        const uint32_t sb  = sbase + (s & 1) * STAGE_B;
        const uint32_t aH = sb + 0 * TILE_B;
        const uint32_t aL = sb + 1 * TILE_B;
        const uint32_t bH = sb + 2 * TILE_B;
        const uint32_t bL = sb + 3 * TILE_B;

        #pragma unroll
        for (int ks = 0; ks < 2; ks++) {
            const int kb = ks * 32;
            uint32_t ah[2][4], al[2][4], bh[4][2], bl[4][2];
            #pragma unroll
            for (int mt = 0; mt < 2; mt++) {
                uint32_t off = (uint32_t)(a_row + mt * 16) * ROW_B + kb + a_koff;
                ldmx4(ah[mt], aH + off);
                ldmx4(al[mt], aL + off);
            }
            #pragma unroll
            for (int nt = 0; nt < 4; nt++) {
                uint32_t off = (uint32_t)(b_row + nt * 8) * ROW_B + kb + b_koff;
                ldmx2(bh[nt], bH + off);
                ldmx2(bl[nt], bL + off);
            }
            #pragma unroll
            for (int mt = 0; mt < 2; mt++)
                #pragma unroll
                for (int nt = 0; nt < 4; nt++) {
                    mma16816(acc[mt][nt], ah[mt], bh[nt]);
                    mma16816(acc[mt][nt], ah[mt], bl[nt]);
                    mma16816(acc[mt][nt], al[mt], bh[nt]);
                }
        }
        __syncthreads();
    }

    #pragma unroll
    for (int mt = 0; mt < 2; mt++) {
        #pragma unroll
        for (int nt = 0; nt < 4; nt++) {
            const int r0 = bm + warp_m + mt * 16 + (lane >> 2);
            const int cl = bn + warp_n + nt * 8 + (lane & 3) * 2;
            const float b0 = bias ? bias[cl]     : 0.f;
            const float b1 = bias ? bias[cl + 1] : 0.f;
            float2 v0 = make_float2(acc[mt][nt][0] + b0, acc[mt][nt][1] + b1);
            float2 v1 = make_float2(acc[mt][nt][2] + b0, acc[mt][nt][3] + b1);
            *(float2*)(C + (size_t)r0 * N + cl)       = v0;
            *(float2*)(C + (size_t)(r0 + 8) * N + cl) = v1;
        }
    }
}

// ---------------------------------------------------------------------------
// RoPE + cache scatter + bf16 mirrors (validated R8)
// ---------------------------------------------------------------------------
__global__ void rope_scatter_kernel(const int* __restrict__ positions,
                                    const int* __restrict__ slot_mapping,
                                    float* __restrict__ cache_out) {
    const int t = blockIdx.x;
    const int tid = threadIdx.x;
    const int pos = positions[t];
    float* row = g_qkv + (size_t)t * QKV_OUT;
    const int slot = slot_mapping[t];
    float* kout = cache_out + (size_t)slot * NKV * DHEAD;
    float* vout = cache_out + (size_t)NSLOTS * NKV * DHEAD + (size_t)slot * NKV * DHEAD;

    if (tid < 64) {
        const float invf = expf(-(float)tid * (logf(10000.f) / 64.f));
        const double ang = (double)pos * (double)invf;
        double dc, ds;
        sincos(ang, &ds, &dc);
        const float c = (float)dc;
        const float s = (float)ds;

        #pragma unroll 4
        for (int h = 0; h < NH; h++) {
            float* x = row + h * DHEAD;
            float x1 = x[tid], x2 = x[tid + 64];
            float r1 = x1 * c - x2 * s;
            float r2 = x2 * c + x1 * s;
            __nv_bfloat16* q = g_qb + ((size_t)t * NH + h) * DHEAD;
            q[tid]      = __float2bfloat16(r1 * SCALE_F);
            q[tid + 64] = __float2bfloat16(r2 * SCALE_F);
        }
        #pragma unroll
        for (int h = 0; h < NKV; h++) {
            float* x = row + (NH + h) * DHEAD;
            float x1 = x[tid], x2 = x[tid + 64];
            float r1 = x1 * c - x2 * s;
            float r2 = x2 * c + x1 * s;
            kout[h * DHEAD + tid]      = r1;
            kout[h * DHEAD + tid + 64] = r2;
            __nv_bfloat16* kb = g_kb + ((size_t)t * NKV + h) * DHEAD;
            kb[tid]      = __float2bfloat16(r1);
            kb[tid + 64] = __float2bfloat16(r2);
        }
    }
    #pragma unroll
    for (int h = 0; h < NKV; h++) {
        float v = row[(NH + NKV + h) * DHEAD + tid];
        vout[h * DHEAD + tid] = v;
        __nv_bfloat16 vh = __float2bfloat16(v);
        const size_t o = ((size_t)t * NKV + h) * DHEAD + tid;
        g_vhb[o] = vh;
        g_vlb[o] = __float2bfloat16(v - __bfloat162float(vh));
    }
}

// ---------------------------------------------------------------------------
// Tensor-core flash attention (exact R8 version — proven at 2576us)
// ---------------------------------------------------------------------------
#define ATT_STRIDE 272
#define ATT_TILE_B (64 * ATT_STRIDE)
#define ATT_SMEM   (4 * ATT_TILE_B)

__global__ __launch_bounds__(128)
void attn_mma(const int* __restrict__ dummy) {
    extern __shared__ char smraw[];
    const uint32_t sb = smem_u32(smraw);
    const uint32_t Qs  = sb;
    const uint32_t Ks  = sb + ATT_TILE_B;
    const uint32_t Vhs = sb + 2 * ATT_TILE_B;
    const uint32_t Vls = sb + 3 * ATT_TILE_B;

    const int qt = blockIdx.x;
    const int bh = blockIdx.y;
    const int b  = bh / NH;
    const int h  = bh % NH;
    const int kv = h / GROUP;
    const int tid  = threadIdx.x;
    const int wid  = tid >> 5;
    const int lane = tid & 31;

    {
        const __nv_bfloat16* gq =
            g_qb + ((size_t)(b * SEQ + qt * 64) * NH + h) * DHEAD;
        #pragma unroll
        for (int i = 0; i < 8; i++) {
            int idx = tid + i * 128;
            int r = idx >> 4, cc = idx & 15;
            cp_async16(Qs + r * ATT_STRIDE + cc * 16,
                       gq + (size_t)r * NH * DHEAD + cc * 8);
        }
        cp_commit();
    }
    auto load_kv = [&](int kt) {
        const size_t base = ((size_t)(b * SEQ + kt * 64) * NKV + kv) * DHEAD;
        #pragma unroll
        for (int i = 0; i < 8; i++) {
            int idx = tid + i * 128;
            int r = idx >> 4, cc = idx & 15;
            const size_t off = base + (size_t)r * NKV * DHEAD + cc * 8;
            const uint32_t d = r * ATT_STRIDE + cc * 16;
            cp_async16(Ks  + d, g_kb  + off);
            cp_async16(Vhs + d, g_vhb + off);
            cp_async16(Vls + d, g_vlb + off);
        }
        cp_commit();
    };
    load_kv(0);
    asm volatile("cp.async.wait_group 0;");
    __syncthreads();

    uint32_t qf[8][4];
    {
        const int a_row  = wid * 16 + ((lane >> 3) & 1) * 8 + (lane & 7);
        const int a_koff = ((lane >> 4) & 1) * 16;
        #pragma unroll
        for (int ks = 0; ks < 8; ks++)
            ldmx4(qf[ks], Qs + (uint32_t)a_row * ATT_STRIDE + ks * 32 + a_koff);
    }

    float o[16][4];
    #pragma unroll
    for (int dt = 0; dt < 16; dt++)
        #pragma unroll
        for (int j = 0; j < 4; j++) o[dt][j] = 0.f;
    float m0 = NEG_BIG, m1 = NEG_BIG, l0 = 0.f, l1 = 0.f;

    const int krow  = lane & 7;
    const int kko   = ((lane >> 3) & 1) * 16;
    const int vrow  = lane & 15;

    for (int kt = 0; kt <= qt; kt++) {
        float accs[8][4];
        #pragma unroll
        for (int nt = 0; nt < 8; nt++)
            #pragma unroll
            for (int j = 0; j < 4; j++) accs[nt][j] = 0.f;

        #pragma unroll
        for (int ks = 0; ks < 8; ks++) {
            #pragma unroll
            for (int nt = 0; nt < 8; nt++) {
                uint32_t kf[2];
                ldmx2(kf, Ks + (uint32_t)(nt * 8 + krow) * ATT_STRIDE + ks * 32 + kko);
                mma16816(accs[nt], qf[ks], kf);
            }
        }

        if (kt == qt) {
            const int r0 = wid * 16 + (lane >> 2);
            const int r1 = r0 + 8;
            #pragma unroll
            for (int nt = 0; nt < 8; nt++) {
                const int c0 = nt * 8 + (lane & 3) * 2;
                if (c0 > r0)     accs[nt][0] = NEG_BIG;
                if (c0 + 1 > r0) accs[nt][1] = NEG_BIG;
                if (c0 > r1)     accs[nt][2] = NEG_BIG;
                if (c0 + 1 > r1) accs[nt][3] = NEG_BIG;
            }
        }

        float tm0 = NEG_BIG, tm1 = NEG_BIG;
        #pragma unroll
        for (int nt = 0; nt < 8; nt++) {
            tm0 = fmaxf(tm0, fmaxf(accs[nt][0], accs[nt][1]));
            tm1 = fmaxf(tm1, fmaxf(accs[nt][2], accs[nt][3]));
        }
        tm0 = fmaxf(tm0, __shfl_xor_sync(0xFFFFFFFF, tm0, 1));
        tm0 = fmaxf(tm0, __shfl_xor_sync(0xFFFFFFFF, tm0, 2));
        tm1 = fmaxf(tm1, __shfl_xor_sync(0xFFFFFFFF, tm1, 1));
        tm1 = fmaxf(tm1, __shfl_xor_sync(0xFFFFFFFF, tm1, 2));
        const float mn0 = fmaxf(m0, tm0);
        const float mn1 = fmaxf(m1, tm1);
        const float sc0 = __expf(m0 - mn0);
        const float sc1 = __expf(m1 - mn1);

        float ls0 = 0.f, ls1 = 0.f;
        #pragma unroll
        for (int nt = 0; nt < 8; nt++) {
            accs[nt][0] = __expf(accs[nt][0] - mn0);
            accs[nt][1] = __expf(accs[nt][1] - mn0);
            accs[nt][2] = __expf(accs[nt][2] - mn1);
            accs[nt][3] = __expf(accs[nt][3] - mn1);
            ls0 += accs[nt][0] + accs[nt][1];
            ls1 += accs[nt][2] + accs[nt][3];
        }
        ls0 += __shfl_xor_sync(0xFFFFFFFF, ls0, 1);
        ls0 += __shfl_xor_sync(0xFFFFFFFF, ls0, 2);
        ls1 += __shfl_xor_sync(0xFFFFFFFF, ls1, 1);
        ls1 += __shfl_xor_sync(0xFFFFFFFF, ls1, 2);
        l0 = l0 * sc0 + ls0;  m0 = mn0;
        l1 = l1 * sc1 + ls1;  m1 = mn1;

        #pragma unroll
        for (int dt = 0; dt < 16; dt++) {
            o[dt][0] *= sc0; o[dt][1] *= sc0;
            o[dt][2] *= sc1; o[dt][3] *= sc1;
        }

        #pragma unroll
        for (int ks = 0; ks < 4; ks++) {
            const int t0 = 2 * ks, t1 = 2 * ks + 1;
            uint32_t pha[4], pla[4];
            #pragma unroll
            for (int q = 0; q < 4; q++) {
                const float x0 = accs[(q & 2) ? t1 : t0][(q & 1) ? 2 : 0];
                const float x1 = accs[(q & 2) ? t1 : t0][(q & 1) ? 3 : 1];
                __nv_bfloat16 h0 = __float2bfloat16(x0);
                __nv_bfloat16 h1 = __float2bfloat16(x1);
                pha[q] = pack_bf2(h0, h1);
                pla[q] = pack_bf2(__float2bfloat16(x0 - __bfloat162float(h0)),
                                  __float2bfloat16(x1 - __bfloat162float(h1)));
            }
            #pragma unroll
            for (int dt = 0; dt < 16; dt++) {
                uint32_t vh[2], vl[2];
                const uint32_t va = (uint32_t)(ks * 16 + vrow) * ATT_STRIDE + dt * 16;
                ldmx2t(vh, Vhs + va);
                ldmx2t(vl, Vls + va);
                mma16816(o[dt], pha, vh);
                mma16816(o[dt], pha, vl);
                mma16816(o[dt], pla, vh);
            }
        }

        if (kt < qt) {
            __syncthreads();
            load_kv(kt + 1);
            asm volatile("cp.async.wait_group 0;");
            __syncthreads();
        }
    }

    const float inv0 = 1.f / l0;
    const float inv1 = 1.f / l1;
    const int tok0 = b * SEQ + qt * 64 + wid * 16 + (lane >> 2);
    const int tok1 = tok0 + 8;
    #pragma unroll
    for (int dt = 0; dt < 16; dt++) {
        const int col = h * DHEAD + dt * 8 + (lane & 3) * 2;
        const float x0 = o[dt][0] * inv0, x1 = o[dt][1] * inv0;
        const float y0 = o[dt][2] * inv1, y1 = o[dt][3] * inv1;
        __nv_bfloat16 xh0 = __float2bfloat16(x0), xh1 = __float2bfloat16(x1);
        __nv_bfloat16 yh0 = __float2bfloat16(y0), yh1 = __float2bfloat16(y1);
        const size_t i0 = (size_t)tok0 * HDIM + col;
        const size_t i1 = (size_t)tok1 * HDIM + col;
        *(uint32_t*)(g_ctx_hi + i0) = pack_bf2(xh0, xh1);
        *(uint32_t*)(g_ctx_lo + i0) = pack_bf2(
            __float2bfloat16(x0 - __bfloat162float(xh0)),
            __float2bfloat16(x1 - __bfloat162float(xh1)));
        *(uint32_t*)(g_ctx_hi + i1) = pack_bf2(yh0, yh1);
        *(uint32_t*)(g_ctx_lo + i1) = pack_bf2(
            __float2bfloat16(y0 - __bfloat162float(yh0)),
            __float2bfloat16(y1 - __bfloat162float(yh1)));
    }
}

// ---------------------------------------------------------------------------
// Launch
// ---------------------------------------------------------------------------
extern "C" void kernel_launch(void* const* d_in, const int* in_sizes, int n_in,
                              void* d_out, int out_size) {
    const int*   positions    = (const int*)  d_in[0];
    const float* hidden       = (const float*)d_in[1];
    const float* kv_cache_in  = (const float*)d_in[2];
    const int*   slot_mapping = (const int*)  d_in[4];
    const float* w_qkv = (const float*)d_in[n_in - 3];
    const float* b_qkv = (const float*)d_in[n_in - 2];
    const float* w_o   = (const float*)d_in[n_in - 1];

    float* out       = (float*)d_out;
    float* cache_out = out + (size_t)T_TOK * HDIM;

    float* qkv_ptr; cudaGetSymbolAddress((void**)&qkv_ptr, g_qkv);
    __nv_bfloat16 *hid_hi, *hid_lo, *wqkv_hi, *wqkv_lo, *wo_hi, *wo_lo, *ctx_hi, *ctx_lo;
    cudaGetSymbolAddress((void**)&hid_hi,  g_hid_hi);
    cudaGetSymbolAddress((void**)&hid_lo,  g_hid_lo);
    cudaGetSymbolAddress((void**)&wqkv_hi, g_wqkv_hi);
    cudaGetSymbolAddress((void**)&wqkv_lo, g_wqkv_lo);
    cudaGetSymbolAddress((void**)&wo_hi,   g_wo_hi);
    cudaGetSymbolAddress((void**)&wo_lo,   g_wo_lo);
    cudaGetSymbolAddress((void**)&ctx_hi,  g_ctx_hi);
    cudaGetSymbolAddress((void**)&ctx_lo,  g_ctx_lo);

    cudaFuncSetAttribute(gemm_bf16x3,
                         cudaFuncAttributeMaxDynamicSharedMemorySize, GSMEM_BYTES);
    cudaFuncSetAttribute(attn_mma,
                         cudaFuncAttributeMaxDynamicSharedMemorySize, ATT_SMEM);

    // 1) Seed output cache with the input cache
    cudaMemcpyAsync(cache_out, kv_cache_in,
                    (size_t)2 * NSLOTS * NKV * DHEAD * sizeof(float),
                    cudaMemcpyDeviceToDevice, 0);

    // 2) Split hidden + w_qkv + w_o into bf16 hi/lo
    {
        int n4 = (T_TOK * HDIM) / 4;
        split_f32_bf16<<<(n4 + 255) / 256, 256>>>((const float4*)hidden,
                                                  (uint2*)hid_hi, (uint2*)hid_lo, n4);
        n4 = (QKV_OUT * HDIM) / 4;
        split_f32_bf16<<<(n4 + 255) / 256, 256>>>((const float4*)w_qkv,
                                                  (uint2*)wqkv_hi, (uint2*)wqkv_lo, n4);
        n4 = (HDIM * HDIM) / 4;
        split_f32_bf16<<<(n4 + 255) / 256, 256>>>((const float4*)w_o,
                                                  (uint2*)wo_hi, (uint2*)wo_lo, n4);
    }

    // 3) QKV projection
    {
        dim3 grid(QKV_OUT / 128, T_TOK / 128);
        gemm_bf16x3<<<grid, 512, GSMEM_BYTES>>>(hid_hi, hid_lo, wqkv_hi, wqkv_lo,
                                                b_qkv, qkv_ptr,
                                                T_TOK, QKV_OUT, HDIM);
    }

    // 4) RoPE + cache scatter + bf16 mirrors
    rope_scatter_kernel<<<T_TOK, 128>>>(positions, slot_mapping, cache_out);

    // 5) Tensor-core flash attention
    {
        dim3 grid(SEQ / 64, BATCH * NH);
        attn_mma<<<grid, 128, ATT_SMEM>>>(nullptr);
    }

    // 6) Output projection
    {
        dim3 grid(HDIM / 128, T_TOK / 128);
        gemm_bf16x3<<<grid, 512, GSMEM_BYTES>>>(ctx_hi, ctx_lo, wo_hi, wo_lo,
                                                nullptr, out,
                                                T_TOK, HDIM, NH * DHEAD);
    }
}

// round 12
// speedup vs baseline: 2.1106x; 2.1106x over previous
#include <cuda_runtime.h>
#include <cuda_bf16.h>
#include <math.h>
#include <stdint.h>

// ---------------------------------------------------------------------------
// Problem constants (Qwen2Attention_11725260718470)
// ---------------------------------------------------------------------------
#define T_TOK   4096
#define HDIM    3584
#define NH      28
#define NKV     4
#define DHEAD   128
#define GROUP   7
#define BATCH   4
#define SEQ     1024
#define QKV_OUT 4608
#define NSLOTS  8192
#define SCALE_F 0.08838834764831845f
#define NEG_BIG (-1e30f)

// ---------------------------------------------------------------------------
// Device scratch
// ---------------------------------------------------------------------------
__device__ float g_qkv [(size_t)T_TOK * QKV_OUT];
__device__ float g_ctx [(size_t)T_TOK * HDIM];      // tf32-rounded fp32
__device__ float g_hid_r [(size_t)T_TOK * HDIM];    // tf32-rounded inputs
__device__ float g_wqkv_r[(size_t)QKV_OUT * HDIM];
__device__ float g_wo_r  [(size_t)HDIM * HDIM];

// bf16 mirrors for attention (written by rope kernel)
__device__ __nv_bfloat16 g_qb [(size_t)T_TOK * NH * DHEAD];
__device__ __nv_bfloat16 g_kb [(size_t)T_TOK * NKV * DHEAD];
__device__ __nv_bfloat16 g_vhb[(size_t)T_TOK * NKV * DHEAD];
__device__ __nv_bfloat16 g_vlb[(size_t)T_TOK * NKV * DHEAD];

// ---------------------------------------------------------------------------
// Baseline-PTX helpers
// ---------------------------------------------------------------------------
__device__ __forceinline__ uint32_t smem_u32(const void* p) {
    uint32_t a;
    asm("{ .reg .u64 t; cvta.to.shared.u64 t, %1; cvt.u32.u64 %0, t; }"
        : "=r"(a) : "l"(p));
    return a;
}
__device__ __forceinline__ void cp_async16(uint32_t dst, const void* src) {
    asm volatile("cp.async.cg.shared.global [%0], [%1], 16;"
                 :: "r"(dst), "l"(src));
}
__device__ __forceinline__ void cp_commit() {
    asm volatile("cp.async.commit_group;");
}
__device__ __forceinline__ void ldmx4(uint32_t* r, uint32_t addr) {
    asm volatile("ldmatrix.sync.aligned.m8n8.x4.shared.b16 {%0,%1,%2,%3}, [%4];"
                 : "=r"(r[0]), "=r"(r[1]), "=r"(r[2]), "=r"(r[3]) : "r"(addr));
}
__device__ __forceinline__ void ldmx2(uint32_t* r, uint32_t addr) {
    asm volatile("ldmatrix.sync.aligned.m8n8.x2.shared.b16 {%0,%1}, [%2];"
                 : "=r"(r[0]), "=r"(r[1]) : "r"(addr));
}
__device__ __forceinline__ void ldmx2t(uint32_t* r, uint32_t addr) {
    asm volatile("ldmatrix.sync.aligned.m8n8.x2.trans.shared.b16 {%0,%1}, [%2];"
                 : "=r"(r[0]), "=r"(r[1]) : "r"(addr));
}
__device__ __forceinline__ void mma16816(float* c, const uint32_t* a, const uint32_t* b) {
    asm volatile(
        "mma.sync.aligned.m16n8k16.row.col.f32.bf16.bf16.f32 "
        "{%0,%1,%2,%3}, {%4,%5,%6,%7}, {%8,%9}, {%0,%1,%2,%3};"
        : "+f"(c[0]), "+f"(c[1]), "+f"(c[2]), "+f"(c[3])
        : "r"(a[0]), "r"(a[1]), "r"(a[2]), "r"(a[3]), "r"(b[0]), "r"(b[1]));
}
__device__ __forceinline__ void mma_tf32(float* c, const uint32_t* a, const uint32_t* b) {
    asm volatile(
        "mma.sync.aligned.m16n8k8.row.col.f32.tf32.tf32.f32 "
        "{%0,%1,%2,%3}, {%4,%5,%6,%7}, {%8,%9}, {%0,%1,%2,%3};"
        : "+f"(c[0]), "+f"(c[1]), "+f"(c[2]), "+f"(c[3])
        : "r"(a[0]), "r"(a[1]), "r"(a[2]), "r"(a[3]), "r"(b[0]), "r"(b[1]));
}
__device__ __forceinline__ uint32_t rna_tf32(float x) {
    uint32_t u;
    asm("cvt.rna.tf32.f32 %0, %1;" : "=r"(u) : "f"(x));
    return u;
}
__device__ __forceinline__ uint32_t pack_bf2(__nv_bfloat16 a, __nv_bfloat16 b) {
    return (uint32_t)__bfloat16_as_ushort(a) | ((uint32_t)__bfloat16_as_ushort(b) << 16);
}

// ---------------------------------------------------------------------------
// Round fp32 -> tf32 bits (rna), elementwise, vectorized
// ---------------------------------------------------------------------------
__global__ void round_tf32(const float4* __restrict__ x, float4* __restrict__ y, int n4) {
    int i = blockIdx.x * blockDim.x + threadIdx.x;
    if (i >= n4) return;
    float4 v = x[i];
    float4 r;
    r.x = __uint_as_float(rna_tf32(v.x));
    r.y = __uint_as_float(rna_tf32(v.y));
    r.z = __uint_as_float(rna_tf32(v.z));
    r.w = __uint_as_float(rna_tf32(v.w));
    y[i] = r;
}

// ---------------------------------------------------------------------------
// TF32 GEMM on mma.sync m16n8k8: C[m,n] = sum_k A[m,k]*B[n,k] (+bias[n]).
// A:[M,K], B:[N,K] fp32 (pre-rounded to tf32 bits). R8 structure: 256 thr,
// 8 warps (2x4), warp tile 64x32, 2-stage cp.async double buffer.
// SMEM rows: 32 fp32 (128B) at 144B stride -> ldmatrix conflict-free.
// ---------------------------------------------------------------------------
#define GBK        32
#define ROW_B      144
#define TILE_B     (128 * ROW_B)         // 18432
#define STAGE_B    (2 * TILE_B)          // A, B = 36864
#define GSMEM_BYTES (2 * STAGE_B)        // 73728

__global__ __launch_bounds__(256, 1)
void gemm_tf32(const float* __restrict__ A, const float* __restrict__ B,
               const float* __restrict__ bias, float* __restrict__ C,
               int M, int N, int K) {
    extern __shared__ char smem[];
    const uint32_t sbase = smem_u32(smem);

    const int tid  = threadIdx.x;
    const int wid  = tid >> 5;
    const int lane = tid & 31;
    const int bm = blockIdx.y * 128;
    const int bn = blockIdx.x * 128;
    const int warp_m = (wid >> 2) * 64;
    const int warp_n = (wid & 3) * 32;

    const float* gsrc[2] = { A + (size_t)bm * K, B + (size_t)bn * K };

    const int NS = K / GBK;

    // 2 tiles x 1024 16B-chunks; 256 threads -> 4 chunks per tile per thread
    auto load_stage = [&](int buf, int k0) {
        const uint32_t sb = sbase + buf * STAGE_B;
        #pragma unroll
        for (int t = 0; t < 2; t++) {
            const float* g = gsrc[t] + k0;
            #pragma unroll
            for (int i = 0; i < 4; i++) {
                int idx = tid + i * 256;       // 0..1023
                int row = idx >> 3;
                int cc  = idx & 7;
                cp_async16(sb + t * TILE_B + row * ROW_B + cc * 16,
                           g + (size_t)row * K + cc * 4);
            }
        }
        cp_commit();
    };

    float acc[4][4][4];
    #pragma unroll
    for (int mt = 0; mt < 4; mt++)
        #pragma unroll
        for (int nt = 0; nt < 4; nt++)
            #pragma unroll
            for (int j = 0; j < 4; j++) acc[mt][nt][j] = 0.f;

    load_stage(0, 0);

    // tf32 ldmatrix lane addressing:
    // A x4: lanes 0-15 -> rows 0-15 at +0B; lanes 16-31 -> rows 0-15 at +16B
    const int arow = lane & 15;
    const int aoff = (lane >> 4) * 16;
    // B x2: lanes 0-7 -> n-rows at +0B; lanes 8-15 -> n-rows at +16B
    const int brow = lane & 7;
    const int boff = ((lane >> 3) & 1) * 16;

    for (int s = 0; s < NS; s++) {
        if (s + 1 < NS) {
            load_stage((s + 1) & 1, (s + 1) * GBK);
            asm volatile("cp.async.wait_group 1;");
        } else {
            asm volatile("cp.async.wait_group 0;");
        }
        __syncthreads();

        const uint32_t sb = sbase + (s & 1) * STAGE_B;
        const uint32_t aB = sb;
        const uint32_t bB = sb + TILE_B;

        #pragma unroll
        for (int ks = 0; ks < 4; ks++) {
            const int kb = ks * 32;             // 8 tf32 = 32 bytes per k-step
            uint32_t af[4][4], bf[4][2];
            #pragma unroll
            for (int mt = 0; mt < 4; mt++) {
                uint32_t off = (uint32_t)(warp_m + mt * 16 + arow) * ROW_B + kb + aoff;
                ldmx4(af[mt], aB + off);
            }
            #pragma unroll
            for (int nt = 0; nt < 4; nt++) {
                uint32_t off = (uint32_t)(warp_n + nt * 8 + brow) * ROW_B + kb + boff;
                ldmx2(bf[nt], bB + off);
            }
            #pragma unroll
            for (int mt = 0; mt < 4; mt++)
                #pragma unroll
                for (int nt = 0; nt < 4; nt++)
                    mma_tf32(acc[mt][nt], af[mt], bf[nt]);
        }
        __syncthreads();
    }

    #pragma unroll
    for (int mt = 0; mt < 4; mt++) {
        #pragma unroll
        for (int nt = 0; nt < 4; nt++) {
            const int r0 = bm + warp_m + mt * 16 + (lane >> 2);
            const int cl = bn + warp_n + nt * 8 + (lane & 3) * 2;
            const float b0 = bias ? bias[cl]     : 0.f;
            const float b1 = bias ? bias[cl + 1] : 0.f;
            float2 v0 = make_float2(acc[mt][nt][0] + b0, acc[mt][nt][1] + b1);
            float2 v1 = make_float2(acc[mt][nt][2] + b0, acc[mt][nt][3] + b1);
            *(float2*)(C + (size_t)r0 * N + cl)       = v0;
            *(float2*)(C + (size_t)(r0 + 8) * N + cl) = v1;
        }
    }
}

// ---------------------------------------------------------------------------
// RoPE + cache scatter + bf16 mirrors (validated R8)
// ---------------------------------------------------------------------------
__global__ void rope_scatter_kernel(const int* __restrict__ positions,
                                    const int* __restrict__ slot_mapping,
                                    float* __restrict__ cache_out) {
    const int t = blockIdx.x;
    const int tid = threadIdx.x;
    const int pos = positions[t];
    float* row = g_qkv + (size_t)t * QKV_OUT;
    const int slot = slot_mapping[t];
    float* kout = cache_out + (size_t)slot * NKV * DHEAD;
    float* vout = cache_out + (size_t)NSLOTS * NKV * DHEAD + (size_t)slot * NKV * DHEAD;

    if (tid < 64) {
        const float invf = expf(-(float)tid * (logf(10000.f) / 64.f));
        const double ang = (double)pos * (double)invf;
        double dc, ds;
        sincos(ang, &ds, &dc);
        const float c = (float)dc;
        const float s = (float)ds;

        #pragma unroll 4
        for (int h = 0; h < NH; h++) {
            float* x = row + h * DHEAD;
            float x1 = x[tid], x2 = x[tid + 64];
            float r1 = x1 * c - x2 * s;
            float r2 = x2 * c + x1 * s;
            __nv_bfloat16* q = g_qb + ((size_t)t * NH + h) * DHEAD;
            q[tid]      = __float2bfloat16(r1 * SCALE_F);
            q[tid + 64] = __float2bfloat16(r2 * SCALE_F);
        }
        #pragma unroll
        for (int h = 0; h < NKV; h++) {
            float* x = row + (NH + h) * DHEAD;
            float x1 = x[tid], x2 = x[tid + 64];
            float r1 = x1 * c - x2 * s;
            float r2 = x2 * c + x1 * s;
            kout[h * DHEAD + tid]      = r1;
            kout[h * DHEAD + tid + 64] = r2;
            __nv_bfloat16* kb = g_kb + ((size_t)t * NKV + h) * DHEAD;
            kb[tid]      = __float2bfloat16(r1);
            kb[tid + 64] = __float2bfloat16(r2);
        }
    }
    #pragma unroll
    for (int h = 0; h < NKV; h++) {
        float v = row[(NH + NKV + h) * DHEAD + tid];
        vout[h * DHEAD + tid] = v;
        __nv_bfloat16 vh = __float2bfloat16(v);
        const size_t o = ((size_t)t * NKV + h) * DHEAD + tid;
        g_vhb[o] = vh;
        g_vlb[o] = __float2bfloat16(v - __bfloat162float(vh));
    }
}

// ---------------------------------------------------------------------------
// Tensor-core flash attention (exact R8 version; epilogue writes tf32-rounded
// fp32 ctx directly for the tf32 O-projection).
// ---------------------------------------------------------------------------
#define ATT_STRIDE 272
#define ATT_TILE_B (64 * ATT_STRIDE)
#define ATT_SMEM   (4 * ATT_TILE_B)

__global__ __launch_bounds__(128)
void attn_mma(const int* __restrict__ dummy) {
    extern __shared__ char smraw[];
    const uint32_t sb = smem_u32(smraw);
    const uint32_t Qs  = sb;
    const uint32_t Ks  = sb + ATT_TILE_B;
    const uint32_t Vhs = sb + 2 * ATT_TILE_B;
    const uint32_t Vls = sb + 3 * ATT_TILE_B;

    const int qt = blockIdx.x;
    const int bh = blockIdx.y;
    const int b  = bh / NH;
    const int h  = bh % NH;
    const int kv = h / GROUP;
    const int tid  = threadIdx.x;
    const int wid  = tid >> 5;
    const int lane = tid & 31;

    {
        const __nv_bfloat16* gq =
            g_qb + ((size_t)(b * SEQ + qt * 64) * NH + h) * DHEAD;
        #pragma unroll
        for (int i = 0; i < 8; i++) {
            int idx = tid + i * 128;
            int r = idx >> 4, cc = idx & 15;
            cp_async16(Qs + r * ATT_STRIDE + cc * 16,
                       gq + (size_t)r * NH * DHEAD + cc * 8);
        }
        cp_commit();
    }
    auto load_kv = [&](int kt) {
        const size_t base = ((size_t)(b * SEQ + kt * 64) * NKV + kv) * DHEAD;
        #pragma unroll
        for (int i = 0; i < 8; i++) {
            int idx = tid + i * 128;
            int r = idx >> 4, cc = idx & 15;
            const size_t off = base + (size_t)r * NKV * DHEAD + cc * 8;
            const uint32_t d = r * ATT_STRIDE + cc * 16;
            cp_async16(Ks  + d, g_kb  + off);
            cp_async16(Vhs + d, g_vhb + off);
            cp_async16(Vls + d, g_vlb + off);
        }
        cp_commit();
    };
    load_kv(0);
    asm volatile("cp.async.wait_group 0;");
    __syncthreads();

    uint32_t qf[8][4];
    {
        const int a_row  = wid * 16 + ((lane >> 3) & 1) * 8 + (lane & 7);
        const int a_koff = ((lane >> 4) & 1) * 16;
        #pragma unroll
        for (int ks = 0; ks < 8; ks++)
            ldmx4(qf[ks], Qs + (uint32_t)a_row * ATT_STRIDE + ks * 32 + a_koff);
    }

    float o[16][4];
    #pragma unroll
    for (int dt = 0; dt < 16; dt++)
        #pragma unroll
        for (int j = 0; j < 4; j++) o[dt][j] = 0.f;
    float m0 = NEG_BIG, m1 = NEG_BIG, l0 = 0.f, l1 = 0.f;

    const int krow  = lane & 7;
    const int kko   = ((lane >> 3) & 1) * 16;
    const int vrow  = lane & 15;

    for (int kt = 0; kt <= qt; kt++) {
        float accs[8][4];
        #pragma unroll
        for (int nt = 0; nt < 8; nt++)
            #pragma unroll
            for (int j = 0; j < 4; j++) accs[nt][j] = 0.f;

        #pragma unroll
        for (int ks = 0; ks < 8; ks++) {
            #pragma unroll
            for (int nt = 0; nt < 8; nt++) {
                uint32_t kf[2];
                ldmx2(kf, Ks + (uint32_t)(nt * 8 + krow) * ATT_STRIDE + ks * 32 + kko);
                mma16816(accs[nt], qf[ks], kf);
            }
        }

        if (kt == qt) {
            const int r0 = wid * 16 + (lane >> 2);
            const int r1 = r0 + 8;
            #pragma unroll
            for (int nt = 0; nt < 8; nt++) {
                const int c0 = nt * 8 + (lane & 3) * 2;
                if (c0 > r0)     accs[nt][0] = NEG_BIG;
                if (c0 + 1 > r0) accs[nt][1] = NEG_BIG;
                if (c0 > r1)     accs[nt][2] = NEG_BIG;
                if (c0 + 1 > r1) accs[nt][3] = NEG_BIG;
            }
        }

        float tm0 = NEG_BIG, tm1 = NEG_BIG;
        #pragma unroll
        for (int nt = 0; nt < 8; nt++) {
            tm0 = fmaxf(tm0, fmaxf(accs[nt][0], accs[nt][1]));
            tm1 = fmaxf(tm1, fmaxf(accs[nt][2], accs[nt][3]));
        }
        tm0 = fmaxf(tm0, __shfl_xor_sync(0xFFFFFFFF, tm0, 1));
        tm0 = fmaxf(tm0, __shfl_xor_sync(0xFFFFFFFF, tm0, 2));
        tm1 = fmaxf(tm1, __shfl_xor_sync(0xFFFFFFFF, tm1, 1));
        tm1 = fmaxf(tm1, __shfl_xor_sync(0xFFFFFFFF, tm1, 2));
        const float mn0 = fmaxf(m0, tm0);
        const float mn1 = fmaxf(m1, tm1);
        const float sc0 = __expf(m0 - mn0);
        const float sc1 = __expf(m1 - mn1);

        float ls0 = 0.f, ls1 = 0.f;
        #pragma unroll
        for (int nt = 0; nt < 8; nt++) {
            accs[nt][0] = __expf(accs[nt][0] - mn0);
            accs[nt][1] = __expf(accs[nt][1] - mn0);
            accs[nt][2] = __expf(accs[nt][2] - mn1);
            accs[nt][3] = __expf(accs[nt][3] - mn1);
            ls0 += accs[nt][0] + accs[nt][1];
            ls1 += accs[nt][2] + accs[nt][3];
        }
        ls0 += __shfl_xor_sync(0xFFFFFFFF, ls0, 1);
        ls0 += __shfl_xor_sync(0xFFFFFFFF, ls0, 2);
        ls1 += __shfl_xor_sync(0xFFFFFFFF, ls1, 1);
        ls1 += __shfl_xor_sync(0xFFFFFFFF, ls1, 2);
        l0 = l0 * sc0 + ls0;  m0 = mn0;
        l1 = l1 * sc1 + ls1;  m1 = mn1;

        #pragma unroll
        for (int dt = 0; dt < 16; dt++) {
            o[dt][0] *= sc0; o[dt][1] *= sc0;
            o[dt][2] *= sc1; o[dt][3] *= sc1;
        }

        #pragma unroll
        for (int ks = 0; ks < 4; ks++) {
            const int t0 = 2 * ks, t1 = 2 * ks + 1;
            uint32_t pha[4], pla[4];
            #pragma unroll
            for (int q = 0; q < 4; q++) {
                const float x0 = accs[(q & 2) ? t1 : t0][(q & 1) ? 2 : 0];
                const float x1 = accs[(q & 2) ? t1 : t0][(q & 1) ? 3 : 1];
                __nv_bfloat16 h0 = __float2bfloat16(x0);
                __nv_bfloat16 h1 = __float2bfloat16(x1);
                pha[q] = pack_bf2(h0, h1);
                pla[q] = pack_bf2(__float2bfloat16(x0 - __bfloat162float(h0)),
                                  __float2bfloat16(x1 - __bfloat162float(h1)));
            }
            #pragma unroll
            for (int dt = 0; dt < 16; dt++) {
                uint32_t vh[2], vl[2];
                const uint32_t va = (uint32_t)(ks * 16 + vrow) * ATT_STRIDE + dt * 16;
                ldmx2t(vh, Vhs + va);
                ldmx2t(vl, Vls + va);
                mma16816(o[dt], pha, vh);
                mma16816(o[dt], pha, vl);
                mma16816(o[dt], pla, vh);
            }
        }

        if (kt < qt) {
            __syncthreads();
            load_kv(kt + 1);
            asm volatile("cp.async.wait_group 0;");
            __syncthreads();
        }
    }

    // epilogue: normalize, round to tf32 bits, write fp32 ctx
    const float inv0 = 1.f / l0;
    const float inv1 = 1.f / l1;
    const int tok0 = b * SEQ + qt * 64 + wid * 16 + (lane >> 2);
    const int tok1 = tok0 + 8;
    #pragma unroll
    for (int dt = 0; dt < 16; dt++) {
        const int col = h * DHEAD + dt * 8 + (lane & 3) * 2;
        float2 w0, w1;
        w0.x = __uint_as_float(rna_tf32(o[dt][0] * inv0));
        w0.y = __uint_as_float(rna_tf32(o[dt][1] * inv0));
        w1.x = __uint_as_float(rna_tf32(o[dt][2] * inv1));
        w1.y = __uint_as_float(rna_tf32(o[dt][3] * inv1));
        *(float2*)(g_ctx + (size_t)tok0 * HDIM + col) = w0;
        *(float2*)(g_ctx + (size_t)tok1 * HDIM + col) = w1;
    }
}

// ---------------------------------------------------------------------------
// Launch
// ---------------------------------------------------------------------------
extern "C" void kernel_launch(void* const* d_in, const int* in_sizes, int n_in,
                              void* d_out, int out_size) {
    const int*   positions    = (const int*)  d_in[0];
    const float* hidden       = (const float*)d_in[1];
    const float* kv_cache_in  = (const float*)d_in[2];
    const int*   slot_mapping = (const int*)  d_in[4];
    const float* w_qkv = (const float*)d_in[n_in - 3];
    const float* b_qkv = (const float*)d_in[n_in - 2];
    const float* w_o   = (const float*)d_in[n_in - 1];

    float* out       = (float*)d_out;
    float* cache_out = out + (size_t)T_TOK * HDIM;

    float *qkv_ptr, *ctx_ptr, *hid_r, *wqkv_r, *wo_r;
    cudaGetSymbolAddress((void**)&qkv_ptr, g_qkv);
    cudaGetSymbolAddress((void**)&ctx_ptr, g_ctx);
    cudaGetSymbolAddress((void**)&hid_r,   g_hid_r);
    cudaGetSymbolAddress((void**)&wqkv_r,  g_wqkv_r);
    cudaGetSymbolAddress((void**)&wo_r,    g_wo_r);

    cudaFuncSetAttribute(gemm_tf32,
                         cudaFuncAttributeMaxDynamicSharedMemorySize, GSMEM_BYTES);
    cudaFuncSetAttribute(attn_mma,
                         cudaFuncAttributeMaxDynamicSharedMemorySize, ATT_SMEM);

    // 1) Seed output cache with the input cache
    cudaMemcpyAsync(cache_out, kv_cache_in,
                    (size_t)2 * NSLOTS * NKV * DHEAD * sizeof(float),
                    cudaMemcpyDeviceToDevice, 0);

    // 2) Round hidden + w_qkv + w_o to tf32 bits (rna)
    {
        int n4 = (T_TOK * HDIM) / 4;
        round_tf32<<<(n4 + 255) / 256, 256>>>((const float4*)hidden,
                                              (float4*)hid_r, n4);
        n4 = (QKV_OUT * HDIM) / 4;
        round_tf32<<<(n4 + 255) / 256, 256>>>((const float4*)w_qkv,
                                              (float4*)wqkv_r, n4);
        n4 = (HDIM * HDIM) / 4;
        round_tf32<<<(n4 + 255) / 256, 256>>>((const float4*)w_o,
                                              (float4*)wo_r, n4);
    }

    // 3) QKV projection (tf32 tensor cores)
    {
        dim3 grid(QKV_OUT / 128, T_TOK / 128);
        gemm_tf32<<<grid, 256, GSMEM_BYTES>>>(hid_r, wqkv_r, b_qkv, qkv_ptr,
                                              T_TOK, QKV_OUT, HDIM);
    }

    // 4) RoPE + cache scatter + bf16 mirrors
    rope_scatter_kernel<<<T_TOK, 128>>>(positions, slot_mapping, cache_out);

    // 5) Tensor-core flash attention -> tf32-rounded fp32 ctx
    {
        dim3 grid(SEQ / 64, BATCH * NH);
        attn_mma<<<grid, 128, ATT_SMEM>>>(nullptr);
    }

    // 6) Output projection (tf32 tensor cores)
    {
        dim3 grid(HDIM / 128, T_TOK / 128);
        gemm_tf32<<<grid, 256, GSMEM_BYTES>>>(ctx_ptr, wo_r, nullptr, out,
                                              T_TOK, HDIM, NH * DHEAD);
    }
}

// round 13
// speedup vs baseline: 2.9778x; 1.4109x over previous
#include <cuda_runtime.h>
#include <cuda_bf16.h>
#include <cuda_fp16.h>
#include <math.h>
#include <stdint.h>

// ---------------------------------------------------------------------------
// Problem constants (Qwen2Attention_11725260718470)
// ---------------------------------------------------------------------------
#define T_TOK   4096
#define HDIM    3584
#define NH      28
#define NKV     4
#define DHEAD   128
#define GROUP   7
#define BATCH   4
#define SEQ     1024
#define QKV_OUT 4608
#define NSLOTS  8192
#define SCALE_F 0.08838834764831845f
#define NEG_BIG (-1e30f)

// ---------------------------------------------------------------------------
// Device scratch
// ---------------------------------------------------------------------------
__device__ float  g_qkv  [(size_t)T_TOK * QKV_OUT];
__device__ __half g_ctx_h[(size_t)T_TOK * HDIM];     // fp16 ctx (attn output)
__device__ __half g_hid_h [(size_t)T_TOK * HDIM];    // fp16 operands for GEMMs
__device__ __half g_wqkv_h[(size_t)QKV_OUT * HDIM];
__device__ __half g_wo_h  [(size_t)HDIM * HDIM];

// bf16 mirrors for attention (written by rope kernel)
__device__ __nv_bfloat16 g_qb [(size_t)T_TOK * NH * DHEAD];
__device__ __nv_bfloat16 g_kb [(size_t)T_TOK * NKV * DHEAD];
__device__ __nv_bfloat16 g_vhb[(size_t)T_TOK * NKV * DHEAD];
__device__ __nv_bfloat16 g_vlb[(size_t)T_TOK * NKV * DHEAD];

// ---------------------------------------------------------------------------
// Baseline-PTX helpers
// ---------------------------------------------------------------------------
__device__ __forceinline__ uint32_t smem_u32(const void* p) {
    uint32_t a;
    asm("{ .reg .u64 t; cvta.to.shared.u64 t, %1; cvt.u32.u64 %0, t; }"
        : "=r"(a) : "l"(p));
    return a;
}
__device__ __forceinline__ void cp_async16(uint32_t dst, const void* src) {
    asm volatile("cp.async.cg.shared.global [%0], [%1], 16;"
                 :: "r"(dst), "l"(src));
}
__device__ __forceinline__ void cp_commit() {
    asm volatile("cp.async.commit_group;");
}
__device__ __forceinline__ void ldmx4(uint32_t* r, uint32_t addr) {
    asm volatile("ldmatrix.sync.aligned.m8n8.x4.shared.b16 {%0,%1,%2,%3}, [%4];"
                 : "=r"(r[0]), "=r"(r[1]), "=r"(r[2]), "=r"(r[3]) : "r"(addr));
}
__device__ __forceinline__ void ldmx2(uint32_t* r, uint32_t addr) {
    asm volatile("ldmatrix.sync.aligned.m8n8.x2.shared.b16 {%0,%1}, [%2];"
                 : "=r"(r[0]), "=r"(r[1]) : "r"(addr));
}
__device__ __forceinline__ void ldmx2t(uint32_t* r, uint32_t addr) {
    asm volatile("ldmatrix.sync.aligned.m8n8.x2.trans.shared.b16 {%0,%1}, [%2];"
                 : "=r"(r[0]), "=r"(r[1]) : "r"(addr));
}
// bf16 mma (attention)
__device__ __forceinline__ void mma16816(float* c, const uint32_t* a, const uint32_t* b) {
    asm volatile(
        "mma.sync.aligned.m16n8k16.row.col.f32.bf16.bf16.f32 "
        "{%0,%1,%2,%3}, {%4,%5,%6,%7}, {%8,%9}, {%0,%1,%2,%3};"
        : "+f"(c[0]), "+f"(c[1]), "+f"(c[2]), "+f"(c[3])
        : "r"(a[0]), "r"(a[1]), "r"(a[2]), "r"(a[3]), "r"(b[0]), "r"(b[1]));
}
// fp16 mma (projection GEMMs)
__device__ __forceinline__ void mma_f16(float* c, const uint32_t* a, const uint32_t* b) {
    asm volatile(
        "mma.sync.aligned.m16n8k16.row.col.f32.f16.f16.f32 "
        "{%0,%1,%2,%3}, {%4,%5,%6,%7}, {%8,%9}, {%0,%1,%2,%3};"
        : "+f"(c[0]), "+f"(c[1]), "+f"(c[2]), "+f"(c[3])
        : "r"(a[0]), "r"(a[1]), "r"(a[2]), "r"(a[3]), "r"(b[0]), "r"(b[1]));
}
__device__ __forceinline__ uint32_t pack_bf2(__nv_bfloat16 a, __nv_bfloat16 b) {
    return (uint32_t)__bfloat16_as_ushort(a) | ((uint32_t)__bfloat16_as_ushort(b) << 16);
}

// ---------------------------------------------------------------------------
// Convert fp32 -> fp16 (rn), vectorized
// ---------------------------------------------------------------------------
__global__ void conv_f16(const float4* __restrict__ x, uint2* __restrict__ y, int n4) {
    int i = blockIdx.x * blockDim.x + threadIdx.x;
    if (i >= n4) return;
    float4 v = x[i];
    __half2 a = __floats2half2_rn(v.x, v.y);
    __half2 b = __floats2half2_rn(v.z, v.w);
    uint2 r;
    r.x = *(uint32_t*)&a;
    r.y = *(uint32_t*)&b;
    y[i] = r;
}

// ---------------------------------------------------------------------------
// FP16 GEMM on mma.sync m16n8k16 (fp32 accum):
// C[m,n] = sum_k A[m,k]*B[n,k] (+bias[n]);  A:[M,K], B:[N,K] fp16.
// R8 structure: 256 threads, 8 warps (2x4), warp tile 64x32, 2-stage buffer.
// SMEM rows: 32 fp16 (64B) at 80B stride -> ldmatrix conflict-free.
// ---------------------------------------------------------------------------
#define GBK        32
#define ROW_B      80
#define TILE_B     (128 * ROW_B)         // 10240
#define STAGE_B    (2 * TILE_B)          // A, B = 20480
#define GSMEM_BYTES (2 * STAGE_B)        // 40960

__global__ __launch_bounds__(256, 1)
void gemm_f16(const __half* __restrict__ A, const __half* __restrict__ B,
              const float* __restrict__ bias, float* __restrict__ C,
              int M, int N, int K) {
    extern __shared__ char smem[];
    const uint32_t sbase = smem_u32(smem);

    const int tid  = threadIdx.x;
    const int wid  = tid >> 5;
    const int lane = tid & 31;
    const int bm = blockIdx.y * 128;
    const int bn = blockIdx.x * 128;
    const int warp_m = (wid >> 2) * 64;
    const int warp_n = (wid & 3) * 32;

    const __half* gsrc[2] = { A + (size_t)bm * K, B + (size_t)bn * K };

    const int NS = K / GBK;

    auto load_stage = [&](int buf, int k0) {
        const uint32_t sb = sbase + buf * STAGE_B;
        #pragma unroll
        for (int t = 0; t < 2; t++) {
            const __half* g = gsrc[t] + k0;
            #pragma unroll
            for (int i = 0; i < 2; i++) {
                int idx = tid + i * 256;   // 0..511
                int row = idx >> 2;
                int cc  = idx & 3;
                cp_async16(sb + t * TILE_B + row * ROW_B + cc * 16,
                           g + (size_t)row * K + cc * 8);
            }
        }
        cp_commit();
    };

    float acc[4][4][4];
    #pragma unroll
    for (int mt = 0; mt < 4; mt++)
        #pragma unroll
        for (int nt = 0; nt < 4; nt++)
            #pragma unroll
            for (int j = 0; j < 4; j++) acc[mt][nt][j] = 0.f;

    load_stage(0, 0);

    const int a_row  = warp_m + ((lane >> 3) & 1) * 8 + (lane & 7);
    const int a_koff = ((lane >> 4) & 1) * 16;
    const int l2     = lane & 15;
    const int b_row  = warp_n + (l2 & 7);
    const int b_koff = ((l2 >> 3) & 1) * 16;

    for (int s = 0; s < NS; s++) {
        if (s + 1 < NS) {
            load_stage((s + 1) & 1, (s + 1) * GBK);
            asm volatile("cp.async.wait_group 1;");
        } else {
            asm volatile("cp.async.wait_group 0;");
        }
        __syncthreads();

        const uint32_t sb = sbase + (s & 1) * STAGE_B;
        const uint32_t aB = sb;
        const uint32_t bB = sb + TILE_B;

        #pragma unroll
        for (int ks = 0; ks < 2; ks++) {
            const int kb = ks * 32;        // 16 fp16 = 32B per k16 step
            uint32_t af[4][4], bf[4][2];
            #pragma unroll
            for (int mt = 0; mt < 4; mt++) {
                uint32_t off = (uint32_t)(a_row + mt * 16) * ROW_B + kb + a_koff;
                ldmx4(af[mt], aB + off);
            }
            #pragma unroll
            for (int nt = 0; nt < 4; nt++) {
                uint32_t off = (uint32_t)(b_row + nt * 8) * ROW_B + kb + b_koff;
                ldmx2(bf[nt], bB + off);
            }
            #pragma unroll
            for (int mt = 0; mt < 4; mt++)
                #pragma unroll
                for (int nt = 0; nt < 4; nt++)
                    mma_f16(acc[mt][nt], af[mt], bf[nt]);
        }
        __syncthreads();
    }

    #pragma unroll
    for (int mt = 0; mt < 4; mt++) {
        #pragma unroll
        for (int nt = 0; nt < 4; nt++) {
            const int r0 = bm + warp_m + mt * 16 + (lane >> 2);
            const int cl = bn + warp_n + nt * 8 + (lane & 3) * 2;
            const float b0 = bias ? bias[cl]     : 0.f;
            const float b1 = bias ? bias[cl + 1] : 0.f;
            float2 v0 = make_float2(acc[mt][nt][0] + b0, acc[mt][nt][1] + b1);
            float2 v1 = make_float2(acc[mt][nt][2] + b0, acc[mt][nt][3] + b1);
            *(float2*)(C + (size_t)r0 * N + cl)       = v0;
            *(float2*)(C + (size_t)(r0 + 8) * N + cl) = v1;
        }
    }
}

// ---------------------------------------------------------------------------
// RoPE + cache scatter + bf16 mirrors (validated R8)
// ---------------------------------------------------------------------------
__global__ void rope_scatter_kernel(const int* __restrict__ positions,
                                    const int* __restrict__ slot_mapping,
                                    float* __restrict__ cache_out) {
    const int t = blockIdx.x;
    const int tid = threadIdx.x;
    const int pos = positions[t];
    float* row = g_qkv + (size_t)t * QKV_OUT;
    const int slot = slot_mapping[t];
    float* kout = cache_out + (size_t)slot * NKV * DHEAD;
    float* vout = cache_out + (size_t)NSLOTS * NKV * DHEAD + (size_t)slot * NKV * DHEAD;

    if (tid < 64) {
        const float invf = expf(-(float)tid * (logf(10000.f) / 64.f));
        const double ang = (double)pos * (double)invf;
        double dc, ds;
        sincos(ang, &ds, &dc);
        const float c = (float)dc;
        const float s = (float)ds;

        #pragma unroll 4
        for (int h = 0; h < NH; h++) {
            float* x = row + h * DHEAD;
            float x1 = x[tid], x2 = x[tid + 64];
            float r1 = x1 * c - x2 * s;
            float r2 = x2 * c + x1 * s;
            __nv_bfloat16* q = g_qb + ((size_t)t * NH + h) * DHEAD;
            q[tid]      = __float2bfloat16(r1 * SCALE_F);
            q[tid + 64] = __float2bfloat16(r2 * SCALE_F);
        }
        #pragma unroll
        for (int h = 0; h < NKV; h++) {
            float* x = row + (NH + h) * DHEAD;
            float x1 = x[tid], x2 = x[tid + 64];
            float r1 = x1 * c - x2 * s;
            float r2 = x2 * c + x1 * s;
            kout[h * DHEAD + tid]      = r1;
            kout[h * DHEAD + tid + 64] = r2;
            __nv_bfloat16* kb = g_kb + ((size_t)t * NKV + h) * DHEAD;
            kb[tid]      = __float2bfloat16(r1);
            kb[tid + 64] = __float2bfloat16(r2);
        }
    }
    #pragma unroll
    for (int h = 0; h < NKV; h++) {
        float v = row[(NH + NKV + h) * DHEAD + tid];
        vout[h * DHEAD + tid] = v;
        __nv_bfloat16 vh = __float2bfloat16(v);
        const size_t o = ((size_t)t * NKV + h) * DHEAD + tid;
        g_vhb[o] = vh;
        g_vlb[o] = __float2bfloat16(v - __bfloat162float(vh));
    }
}

// ---------------------------------------------------------------------------
// Tensor-core flash attention (R8 core; epilogue writes fp16 ctx)
// ---------------------------------------------------------------------------
#define ATT_STRIDE 272
#define ATT_TILE_B (64 * ATT_STRIDE)
#define ATT_SMEM   (4 * ATT_TILE_B)

__global__ __launch_bounds__(128)
void attn_mma(const int* __restrict__ dummy) {
    extern __shared__ char smraw[];
    const uint32_t sb = smem_u32(smraw);
    const uint32_t Qs  = sb;
    const uint32_t Ks  = sb + ATT_TILE_B;
    const uint32_t Vhs = sb + 2 * ATT_TILE_B;
    const uint32_t Vls = sb + 3 * ATT_TILE_B;

    const int qt = blockIdx.x;
    const int bh = blockIdx.y;
    const int b  = bh / NH;
    const int h  = bh % NH;
    const int kv = h / GROUP;
    const int tid  = threadIdx.x;
    const int wid  = tid >> 5;
    const int lane = tid & 31;

    {
        const __nv_bfloat16* gq =
            g_qb + ((size_t)(b * SEQ + qt * 64) * NH + h) * DHEAD;
        #pragma unroll
        for (int i = 0; i < 8; i++) {
            int idx = tid + i * 128;
            int r = idx >> 4, cc = idx & 15;
            cp_async16(Qs + r * ATT_STRIDE + cc * 16,
                       gq + (size_t)r * NH * DHEAD + cc * 8);
        }
        cp_commit();
    }
    auto load_kv = [&](int kt) {
        const size_t base = ((size_t)(b * SEQ + kt * 64) * NKV + kv) * DHEAD;
        #pragma unroll
        for (int i = 0; i < 8; i++) {
            int idx = tid + i * 128;
            int r = idx >> 4, cc = idx & 15;
            const size_t off = base + (size_t)r * NKV * DHEAD + cc * 8;
            const uint32_t d = r * ATT_STRIDE + cc * 16;
            cp_async16(Ks  + d, g_kb  + off);
            cp_async16(Vhs + d, g_vhb + off);
            cp_async16(Vls + d, g_vlb + off);
        }
        cp_commit();
    };
    load_kv(0);
    asm volatile("cp.async.wait_group 0;");
    __syncthreads();

    uint32_t qf[8][4];
    {
        const int a_row  = wid * 16 + ((lane >> 3) & 1) * 8 + (lane & 7);
        const int a_koff = ((lane >> 4) & 1) * 16;
        #pragma unroll
        for (int ks = 0; ks < 8; ks++)
            ldmx4(qf[ks], Qs + (uint32_t)a_row * ATT_STRIDE + ks * 32 + a_koff);
    }

    float o[16][4];
    #pragma unroll
    for (int dt = 0; dt < 16; dt++)
        #pragma unroll
        for (int j = 0; j < 4; j++) o[dt][j] = 0.f;
    float m0 = NEG_BIG, m1 = NEG_BIG, l0 = 0.f, l1 = 0.f;

    const int krow  = lane & 7;
    const int kko   = ((lane >> 3) & 1) * 16;
    const int vrow  = lane & 15;

    for (int kt = 0; kt <= qt; kt++) {
        float accs[8][4];
        #pragma unroll
        for (int nt = 0; nt < 8; nt++)
            #pragma unroll
            for (int j = 0; j < 4; j++) accs[nt][j] = 0.f;

        #pragma unroll
        for (int ks = 0; ks < 8; ks++) {
            #pragma unroll
            for (int nt = 0; nt < 8; nt++) {
                uint32_t kf[2];
                ldmx2(kf, Ks + (uint32_t)(nt * 8 + krow) * ATT_STRIDE + ks * 32 + kko);
                mma16816(accs[nt], qf[ks], kf);
            }
        }

        if (kt == qt) {
            const int r0 = wid * 16 + (lane >> 2);
            const int r1 = r0 + 8;
            #pragma unroll
            for (int nt = 0; nt < 8; nt++) {
                const int c0 = nt * 8 + (lane & 3) * 2;
                if (c0 > r0)     accs[nt][0] = NEG_BIG;
                if (c0 + 1 > r0) accs[nt][1] = NEG_BIG;
                if (c0 > r1)     accs[nt][2] = NEG_BIG;
                if (c0 + 1 > r1) accs[nt][3] = NEG_BIG;
            }
        }

        float tm0 = NEG_BIG, tm1 = NEG_BIG;
        #pragma unroll
        for (int nt = 0; nt < 8; nt++) {
            tm0 = fmaxf(tm0, fmaxf(accs[nt][0], accs[nt][1]));
            tm1 = fmaxf(tm1, fmaxf(accs[nt][2], accs[nt][3]));
        }
        tm0 = fmaxf(tm0, __shfl_xor_sync(0xFFFFFFFF, tm0, 1));
        tm0 = fmaxf(tm0, __shfl_xor_sync(0xFFFFFFFF, tm0, 2));
        tm1 = fmaxf(tm1, __shfl_xor_sync(0xFFFFFFFF, tm1, 1));
        tm1 = fmaxf(tm1, __shfl_xor_sync(0xFFFFFFFF, tm1, 2));
        const float mn0 = fmaxf(m0, tm0);
        const float mn1 = fmaxf(m1, tm1);
        const float sc0 = __expf(m0 - mn0);
        const float sc1 = __expf(m1 - mn1);

        float ls0 = 0.f, ls1 = 0.f;
        #pragma unroll
        for (int nt = 0; nt < 8; nt++) {
            accs[nt][0] = __expf(accs[nt][0] - mn0);
            accs[nt][1] = __expf(accs[nt][1] - mn0);
            accs[nt][2] = __expf(accs[nt][2] - mn1);
            accs[nt][3] = __expf(accs[nt][3] - mn1);
            ls0 += accs[nt][0] + accs[nt][1];
            ls1 += accs[nt][2] + accs[nt][3];
        }
        ls0 += __shfl_xor_sync(0xFFFFFFFF, ls0, 1);
        ls0 += __shfl_xor_sync(0xFFFFFFFF, ls0, 2);
        ls1 += __shfl_xor_sync(0xFFFFFFFF, ls1, 1);
        ls1 += __shfl_xor_sync(0xFFFFFFFF, ls1, 2);
        l0 = l0 * sc0 + ls0;  m0 = mn0;
        l1 = l1 * sc1 + ls1;  m1 = mn1;

        #pragma unroll
        for (int dt = 0; dt < 16; dt++) {
            o[dt][0] *= sc0; o[dt][1] *= sc0;
            o[dt][2] *= sc1; o[dt][3] *= sc1;
        }

        #pragma unroll
        for (int ks = 0; ks < 4; ks++) {
            const int t0 = 2 * ks, t1 = 2 * ks + 1;
            uint32_t pha[4], pla[4];
            #pragma unroll
            for (int q = 0; q < 4; q++) {
                const float x0 = accs[(q & 2) ? t1 : t0][(q & 1) ? 2 : 0];
                const float x1 = accs[(q & 2) ? t1 : t0][(q & 1) ? 3 : 1];
                __nv_bfloat16 h0 = __float2bfloat16(x0);
                __nv_bfloat16 h1 = __float2bfloat16(x1);
                pha[q] = pack_bf2(h0, h1);
                pla[q] = pack_bf2(__float2bfloat16(x0 - __bfloat162float(h0)),
                                  __float2bfloat16(x1 - __bfloat162float(h1)));
            }
            #pragma unroll
            for (int dt = 0; dt < 16; dt++) {
                uint32_t vh[2], vl[2];
                const uint32_t va = (uint32_t)(ks * 16 + vrow) * ATT_STRIDE + dt * 16;
                ldmx2t(vh, Vhs + va);
                ldmx2t(vl, Vls + va);
                mma16816(o[dt], pha, vh);
                mma16816(o[dt], pha, vl);
                mma16816(o[dt], pla, vh);
            }
        }

        if (kt < qt) {
            __syncthreads();
            load_kv(kt + 1);
            asm volatile("cp.async.wait_group 0;");
            __syncthreads();
        }
    }

    // epilogue: normalize, write fp16 ctx
    const float inv0 = 1.f / l0;
    const float inv1 = 1.f / l1;
    const int tok0 = b * SEQ + qt * 64 + wid * 16 + (lane >> 2);
    const int tok1 = tok0 + 8;
    #pragma unroll
    for (int dt = 0; dt < 16; dt++) {
        const int col = h * DHEAD + dt * 8 + (lane & 3) * 2;
        __half2 w0 = __floats2half2_rn(o[dt][0] * inv0, o[dt][1] * inv0);
        __half2 w1 = __floats2half2_rn(o[dt][2] * inv1, o[dt][3] * inv1);
        *(uint32_t*)(g_ctx_h + (size_t)tok0 * HDIM + col) = *(uint32_t*)&w0;
        *(uint32_t*)(g_ctx_h + (size_t)tok1 * HDIM + col) = *(uint32_t*)&w1;
    }
}

// ---------------------------------------------------------------------------
// Launch
// ---------------------------------------------------------------------------
extern "C" void kernel_launch(void* const* d_in, const int* in_sizes, int n_in,
                              void* d_out, int out_size) {
    const int*   positions    = (const int*)  d_in[0];
    const float* hidden       = (const float*)d_in[1];
    const float* kv_cache_in  = (const float*)d_in[2];
    const int*   slot_mapping = (const int*)  d_in[4];
    const float* w_qkv = (const float*)d_in[n_in - 3];
    const float* b_qkv = (const float*)d_in[n_in - 2];
    const float* w_o   = (const float*)d_in[n_in - 1];

    float* out       = (float*)d_out;
    float* cache_out = out + (size_t)T_TOK * HDIM;

    float* qkv_ptr;
    __half *ctx_h, *hid_h, *wqkv_h, *wo_h;
    cudaGetSymbolAddress((void**)&qkv_ptr, g_qkv);
    cudaGetSymbolAddress((void**)&ctx_h,   g_ctx_h);
    cudaGetSymbolAddress((void**)&hid_h,   g_hid_h);
    cudaGetSymbolAddress((void**)&wqkv_h,  g_wqkv_h);
    cudaGetSymbolAddress((void**)&wo_h,    g_wo_h);

    cudaFuncSetAttribute(gemm_f16,
                         cudaFuncAttributeMaxDynamicSharedMemorySize, GSMEM_BYTES);
    cudaFuncSetAttribute(attn_mma,
                         cudaFuncAttributeMaxDynamicSharedMemorySize, ATT_SMEM);

    // 1) Seed output cache with the input cache
    cudaMemcpyAsync(cache_out, kv_cache_in,
                    (size_t)2 * NSLOTS * NKV * DHEAD * sizeof(float),
                    cudaMemcpyDeviceToDevice, 0);

    // 2) Convert hidden + w_qkv + w_o to fp16
    {
        int n4 = (T_TOK * HDIM) / 4;
        conv_f16<<<(n4 + 255) / 256, 256>>>((const float4*)hidden,
                                            (uint2*)hid_h, n4);
        n4 = (QKV_OUT * HDIM) / 4;
        conv_f16<<<(n4 + 255) / 256, 256>>>((const float4*)w_qkv,
                                            (uint2*)wqkv_h, n4);
        n4 = (HDIM * HDIM) / 4;
        conv_f16<<<(n4 + 255) / 256, 256>>>((const float4*)w_o,
                                            (uint2*)wo_h, n4);
    }

    // 3) QKV projection (fp16 tensor cores)
    {
        dim3 grid(QKV_OUT / 128, T_TOK / 128);
        gemm_f16<<<grid, 256, GSMEM_BYTES>>>(hid_h, wqkv_h, b_qkv, qkv_ptr,
                                             T_TOK, QKV_OUT, HDIM);
    }

    // 4) RoPE + cache scatter + bf16 mirrors
    rope_scatter_kernel<<<T_TOK, 128>>>(positions, slot_mapping, cache_out);

    // 5) Tensor-core flash attention -> fp16 ctx
    {
        dim3 grid(SEQ / 64, BATCH * NH);
        attn_mma<<<grid, 128, ATT_SMEM>>>(nullptr);
    }

    // 6) Output projection (fp16 tensor cores)
    {
        dim3 grid(HDIM / 128, T_TOK / 128);
        gemm_f16<<<grid, 256, GSMEM_BYTES>>>(ctx_h, wo_h, nullptr, out,
                                             T_TOK, HDIM, NH * DHEAD);
    }
}

// round 15
// speedup vs baseline: 3.5329x; 1.1864x over previous
#include <cuda_runtime.h>
#include <cuda_bf16.h>
#include <cuda_fp16.h>
#include <math.h>
#include <stdint.h>

// ---------------------------------------------------------------------------
// Problem constants (Qwen2Attention_11725260718470)
// ---------------------------------------------------------------------------
#define T_TOK   4096
#define HDIM    3584
#define NH      28
#define NKV     4
#define DHEAD   128
#define GROUP   7
#define BATCH   4
#define SEQ     1024
#define QKV_OUT 4608
#define NSLOTS  8192
#define SCALE_F 0.08838834764831845f
#define NEG_BIG (-1e30f)

// ---------------------------------------------------------------------------
// Device scratch
// ---------------------------------------------------------------------------
__device__ float  g_qkv  [(size_t)T_TOK * QKV_OUT];
__device__ __half g_ctx_h[(size_t)T_TOK * HDIM];
__device__ __half g_hid_h [(size_t)T_TOK * HDIM];
__device__ __half g_wqkv_h[(size_t)QKV_OUT * HDIM];
__device__ __half g_wo_h  [(size_t)HDIM * HDIM];

// bf16 mirrors for attention (written by rope kernel)
__device__ __nv_bfloat16 g_qb [(size_t)T_TOK * NH * DHEAD];
__device__ __nv_bfloat16 g_kb [(size_t)T_TOK * NKV * DHEAD];
__device__ __nv_bfloat16 g_vhb[(size_t)T_TOK * NKV * DHEAD];
__device__ __nv_bfloat16 g_vlb[(size_t)T_TOK * NKV * DHEAD];

// ---------------------------------------------------------------------------
// Baseline-PTX helpers
// ---------------------------------------------------------------------------
__device__ __forceinline__ uint32_t smem_u32(const void* p) {
    uint32_t a;
    asm("{ .reg .u64 t; cvta.to.shared.u64 t, %1; cvt.u32.u64 %0, t; }"
        : "=r"(a) : "l"(p));
    return a;
}
__device__ __forceinline__ void cp_async16(uint32_t dst, const void* src) {
    asm volatile("cp.async.cg.shared.global [%0], [%1], 16;"
                 :: "r"(dst), "l"(src));
}
__device__ __forceinline__ void cp_commit() {
    asm volatile("cp.async.commit_group;");
}
__device__ __forceinline__ void ldmx4(uint32_t* r, uint32_t addr) {
    asm volatile("ldmatrix.sync.aligned.m8n8.x4.shared.b16 {%0,%1,%2,%3}, [%4];"
                 : "=r"(r[0]), "=r"(r[1]), "=r"(r[2]), "=r"(r[3]) : "r"(addr));
}
__device__ __forceinline__ void ldmx2(uint32_t* r, uint32_t addr) {
    asm volatile("ldmatrix.sync.aligned.m8n8.x2.shared.b16 {%0,%1}, [%2];"
                 : "=r"(r[0]), "=r"(r[1]) : "r"(addr));
}
__device__ __forceinline__ void ldmx2t(uint32_t* r, uint32_t addr) {
    asm volatile("ldmatrix.sync.aligned.m8n8.x2.trans.shared.b16 {%0,%1}, [%2];"
                 : "=r"(r[0]), "=r"(r[1]) : "r"(addr));
}
// bf16 mma (attention)
__device__ __forceinline__ void mma16816(float* c, const uint32_t* a, const uint32_t* b) {
    asm volatile(
        "mma.sync.aligned.m16n8k16.row.col.f32.bf16.bf16.f32 "
        "{%0,%1,%2,%3}, {%4,%5,%6,%7}, {%8,%9}, {%0,%1,%2,%3};"
        : "+f"(c[0]), "+f"(c[1]), "+f"(c[2]), "+f"(c[3])
        : "r"(a[0]), "r"(a[1]), "r"(a[2]), "r"(a[3]), "r"(b[0]), "r"(b[1]));
}
// fp16 mma (projection GEMMs)
__device__ __forceinline__ void mma_f16(float* c, const uint32_t* a, const uint32_t* b) {
    asm volatile(
        "mma.sync.aligned.m16n8k16.row.col.f32.f16.f16.f32 "
        "{%0,%1,%2,%3}, {%4,%5,%6,%7}, {%8,%9}, {%0,%1,%2,%3};"
        : "+f"(c[0]), "+f"(c[1]), "+f"(c[2]), "+f"(c[3])
        : "r"(a[0]), "r"(a[1]), "r"(a[2]), "r"(a[3]), "r"(b[0]), "r"(b[1]));
}
__device__ __forceinline__ uint32_t pack_bf2(__nv_bfloat16 a, __nv_bfloat16 b) {
    return (uint32_t)__bfloat16_as_ushort(a) | ((uint32_t)__bfloat16_as_ushort(b) << 16);
}

// ---------------------------------------------------------------------------
// Convert fp32 -> fp16 (rn), vectorized
// ---------------------------------------------------------------------------
__global__ void conv_f16(const float4* __restrict__ x, uint2* __restrict__ y, int n4) {
    int i = blockIdx.x * blockDim.x + threadIdx.x;
    if (i >= n4) return;
    float4 v = x[i];
    __half2 a = __floats2half2_rn(v.x, v.y);
    __half2 b = __floats2half2_rn(v.z, v.w);
    uint2 r;
    r.x = *(uint32_t*)&a;
    r.y = *(uint32_t*)&b;
    y[i] = r;
}

// ---------------------------------------------------------------------------
// FP16 GEMM on mma.sync m16n8k16 (fp32 accum) — GBK=64 (amortize per-stage
// overhead over 2x the MMA work; 56 stages instead of 112).
// C[m,n] = sum_k A[m,k]*B[n,k] (+bias[n]);  A:[M,K], B:[N,K] fp16.
// 256 threads, 8 warps (2x4), warp tile 64x32, 2-stage cp.async buffer.
// SMEM rows: 64 fp16 (128B) at 144B stride -> ldmatrix conflict-free
// (row r starts at bank 4r mod 32; distinct across any 8 consecutive rows).
// ---------------------------------------------------------------------------
#define GBK        64
#define ROW_B      144
#define TILE_B     (128 * ROW_B)         // 18432
#define STAGE_B    (2 * TILE_B)          // A, B = 36864
#define GSMEM_BYTES (2 * STAGE_B)        // 73728

__global__ __launch_bounds__(256, 1)
void gemm_f16(const __half* __restrict__ A, const __half* __restrict__ B,
              const float* __restrict__ bias, float* __restrict__ C,
              int M, int N, int K) {
    extern __shared__ char smem[];
    const uint32_t sbase = smem_u32(smem);

    const int tid  = threadIdx.x;
    const int wid  = tid >> 5;
    const int lane = tid & 31;
    const int bm = blockIdx.y * 128;
    const int bn = blockIdx.x * 128;
    const int warp_m = (wid >> 2) * 64;
    const int warp_n = (wid & 3) * 32;

    const __half* gsrc[2] = { A + (size_t)bm * K, B + (size_t)bn * K };

    const int NS = K / GBK;

    // per stage: 2 tiles x (128 rows x 8 chunks of 16B) = 2048 chunks,
    // 256 threads -> 4 chunks per tile per thread
    auto load_stage = [&](int buf, int k0) {
        const uint32_t sb = sbase + buf * STAGE_B;
        #pragma unroll
        for (int t = 0; t < 2; t++) {
            const __half* g = gsrc[t] + k0;
            #pragma unroll
            for (int i = 0; i < 4; i++) {
                int idx = tid + i * 256;       // 0..1023
                int row = idx >> 3;
                int cc  = idx & 7;
                cp_async16(sb + t * TILE_B + row * ROW_B + cc * 16,
                           g + (size_t)row * K + cc * 8);
            }
        }
        cp_commit();
    };

    float acc[4][4][4];
    #pragma unroll
    for (int mt = 0; mt < 4; mt++)
        #pragma unroll
        for (int nt = 0; nt < 4; nt++)
            #pragma unroll
            for (int j = 0; j < 4; j++) acc[mt][nt][j] = 0.f;

    load_stage(0, 0);

    const int a_row  = warp_m + ((lane >> 3) & 1) * 8 + (lane & 7);
    const int a_koff = ((lane >> 4) & 1) * 16;
    const int l2     = lane & 15;
    const int b_row  = warp_n + (l2 & 7);
    const int b_koff = ((l2 >> 3) & 1) * 16;

    for (int s = 0; s < NS; s++) {
        if (s + 1 < NS) {
            load_stage((s + 1) & 1, (s + 1) * GBK);
            asm volatile("cp.async.wait_group 1;");
        } else {
            asm volatile("cp.async.wait_group 0;");
        }
        __syncthreads();

        const uint32_t sb = sbase + (s & 1) * STAGE_B;
        const uint32_t aB = sb;
        const uint32_t bB = sb + TILE_B;

        #pragma unroll
        for (int ks = 0; ks < 4; ks++) {
            const int kb = ks * 32;        // 16 fp16 = 32B per k16 step
            uint32_t af[4][4], bf[4][2];
            #pragma unroll
            for (int mt = 0; mt < 4; mt++) {
                uint32_t off = (uint32_t)(a_row + mt * 16) * ROW_B + kb + a_koff;
                ldmx4(af[mt], aB + off);
            }
            #pragma unroll
            for (int nt = 0; nt < 4; nt++) {
                uint32_t off = (uint32_t)(b_row + nt * 8) * ROW_B + kb + b_koff;
                ldmx2(bf[nt], bB + off);
            }
            #pragma unroll
            for (int mt = 0; mt < 4; mt++)
                #pragma unroll
                for (int nt = 0; nt < 4; nt++)
                    mma_f16(acc[mt][nt], af[mt], bf[nt]);
        }
        __syncthreads();
    }

    #pragma unroll
    for (int mt = 0; mt < 4; mt++) {
        #pragma unroll
        for (int nt = 0; nt < 4; nt++) {
            const int r0 = bm + warp_m + mt * 16 + (lane >> 2);
            const int cl = bn + warp_n + nt * 8 + (lane & 3) * 2;
            const float b0 = bias ? bias[cl]     : 0.f;
            const float b1 = bias ? bias[cl + 1] : 0.f;
            float2 v0 = make_float2(acc[mt][nt][0] + b0, acc[mt][nt][1] + b1);
            float2 v1 = make_float2(acc[mt][nt][2] + b0, acc[mt][nt][3] + b1);
            *(float2*)(C + (size_t)r0 * N + cl)       = v0;
            *(float2*)(C + (size_t)(r0 + 8) * N + cl) = v1;
        }
    }
}

// ---------------------------------------------------------------------------
// RoPE + cache scatter + bf16 mirrors (validated R8)
// ---------------------------------------------------------------------------
__global__ void rope_scatter_kernel(const int* __restrict__ positions,
                                    const int* __restrict__ slot_mapping,
                                    float* __restrict__ cache_out) {
    const int t = blockIdx.x;
    const int tid = threadIdx.x;
    const int pos = positions[t];
    float* row = g_qkv + (size_t)t * QKV_OUT;
    const int slot = slot_mapping[t];
    float* kout = cache_out + (size_t)slot * NKV * DHEAD;
    float* vout = cache_out + (size_t)NSLOTS * NKV * DHEAD + (size_t)slot * NKV * DHEAD;

    if (tid < 64) {
        const float invf = expf(-(float)tid * (logf(10000.f) / 64.f));
        const double ang = (double)pos * (double)invf;
        double dc, ds;
        sincos(ang, &ds, &dc);
        const float c = (float)dc;
        const float s = (float)ds;

        #pragma unroll 4
        for (int h = 0; h < NH; h++) {
            float* x = row + h * DHEAD;
            float x1 = x[tid], x2 = x[tid + 64];
            float r1 = x1 * c - x2 * s;
            float r2 = x2 * c + x1 * s;
            __nv_bfloat16* q = g_qb + ((size_t)t * NH + h) * DHEAD;
            q[tid]      = __float2bfloat16(r1 * SCALE_F);
            q[tid + 64] = __float2bfloat16(r2 * SCALE_F);
        }
        #pragma unroll
        for (int h = 0; h < NKV; h++) {
            float* x = row + (NH + h) * DHEAD;
            float x1 = x[tid], x2 = x[tid + 64];
            float r1 = x1 * c - x2 * s;
            float r2 = x2 * c + x1 * s;
            kout[h * DHEAD + tid]      = r1;
            kout[h * DHEAD + tid + 64] = r2;
            __nv_bfloat16* kb = g_kb + ((size_t)t * NKV + h) * DHEAD;
            kb[tid]      = __float2bfloat16(r1);
            kb[tid + 64] = __float2bfloat16(r2);
        }
    }
    #pragma unroll
    for (int h = 0; h < NKV; h++) {
        float v = row[(NH + NKV + h) * DHEAD + tid];
        vout[h * DHEAD + tid] = v;
        __nv_bfloat16 vh = __float2bfloat16(v);
        const size_t o = ((size_t)t * NKV + h) * DHEAD + tid;
        g_vhb[o] = vh;
        g_vlb[o] = __float2bfloat16(v - __bfloat162float(vh));
    }
}

// ---------------------------------------------------------------------------
// Tensor-core flash attention (R8 core; epilogue writes fp16 ctx)
// ---------------------------------------------------------------------------
#define ATT_STRIDE 272
#define ATT_TILE_B (64 * ATT_STRIDE)
#define ATT_SMEM   (4 * ATT_TILE_B)

__global__ __launch_bounds__(128)
void attn_mma(const int* __restrict__ dummy) {
    extern __shared__ char smraw[];
    const uint32_t sb = smem_u32(smraw);
    const uint32_t Qs  = sb;
    const uint32_t Ks  = sb + ATT_TILE_B;
    const uint32_t Vhs = sb + 2 * ATT_TILE_B;
    const uint32_t Vls = sb + 3 * ATT_TILE_B;

    const int qt = blockIdx.x;
    const int bh = blockIdx.y;
    const int b  = bh / NH;
    const int h  = bh % NH;
    const int kv = h / GROUP;
    const int tid  = threadIdx.x;
    const int wid  = tid >> 5;
    const int lane = tid & 31;

    {
        const __nv_bfloat16* gq =
            g_qb + ((size_t)(b * SEQ + qt * 64) * NH + h) * DHEAD;
        #pragma unroll
        for (int i = 0; i < 8; i++) {
            int idx = tid + i * 128;
            int r = idx >> 4, cc = idx & 15;
            cp_async16(Qs + r * ATT_STRIDE + cc * 16,
                       gq + (size_t)r * NH * DHEAD + cc * 8);
        }
        cp_commit();
    }
    auto load_kv = [&](int kt) {
        const size_t base = ((size_t)(b * SEQ + kt * 64) * NKV + kv) * DHEAD;
        #pragma unroll
        for (int i = 0; i < 8; i++) {
            int idx = tid + i * 128;
            int r = idx >> 4, cc = idx & 15;
            const size_t off = base + (size_t)r * NKV * DHEAD + cc * 8;
            const uint32_t d = r * ATT_STRIDE + cc * 16;
            cp_async16(Ks  + d, g_kb  + off);
            cp_async16(Vhs + d, g_vhb + off);
            cp_async16(Vls + d, g_vlb + off);
        }
        cp_commit();
    };
    load_kv(0);
    asm volatile("cp.async.wait_group 0;");
    __syncthreads();

    uint32_t qf[8][4];
    {
        const int a_row  = wid * 16 + ((lane >> 3) & 1) * 8 + (lane & 7);
        const int a_koff = ((lane >> 4) & 1) * 16;
        #pragma unroll
        for (int ks = 0; ks < 8; ks++)
            ldmx4(qf[ks], Qs + (uint32_t)a_row * ATT_STRIDE + ks * 32 + a_koff);
    }

    float o[16][4];
    #pragma unroll
    for (int dt = 0; dt < 16; dt++)
        #pragma unroll
        for (int j = 0; j < 4; j++) o[dt][j] = 0.f;
    float m0 = NEG_BIG, m1 = NEG_BIG, l0 = 0.f, l1 = 0.f;

    const int krow  = lane & 7;
    const int kko   = ((lane >> 3) & 1) * 16;
    const int vrow  = lane & 15;

    for (int kt = 0; kt <= qt; kt++) {
        float accs[8][4];
        #pragma unroll
        for (int nt = 0; nt < 8; nt++)
            #pragma unroll
            for (int j = 0; j < 4; j++) accs[nt][j] = 0.f;

        #pragma unroll
        for (int ks = 0; ks < 8; ks++) {
            #pragma unroll
            for (int nt = 0; nt < 8; nt++) {
                uint32_t kf[2];
                ldmx2(kf, Ks + (uint32_t)(nt * 8 + krow) * ATT_STRIDE + ks * 32 + kko);
                mma16816(accs[nt], qf[ks], kf);
            }
        }

        if (kt == qt) {
            const int r0 = wid * 16 + (lane >> 2);
            const int r1 = r0 + 8;
            #pragma unroll
            for (int nt = 0; nt < 8; nt++) {
                const int c0 = nt * 8 + (lane & 3) * 2;
                if (c0 > r0)     accs[nt][0] = NEG_BIG;
                if (c0 + 1 > r0) accs[nt][1] = NEG_BIG;
                if (c0 > r1)     accs[nt][2] = NEG_BIG;
                if (c0 + 1 > r1) accs[nt][3] = NEG_BIG;
            }
        }

        float tm0 = NEG_BIG, tm1 = NEG_BIG;
        #pragma unroll
        for (int nt = 0; nt < 8; nt++) {
            tm0 = fmaxf(tm0, fmaxf(accs[nt][0], accs[nt][1]));
            tm1 = fmaxf(tm1, fmaxf(accs[nt][2], accs[nt][3]));
        }
        tm0 = fmaxf(tm0, __shfl_xor_sync(0xFFFFFFFF, tm0, 1));
        tm0 = fmaxf(tm0, __shfl_xor_sync(0xFFFFFFFF, tm0, 2));
        tm1 = fmaxf(tm1, __shfl_xor_sync(0xFFFFFFFF, tm1, 1));
        tm1 = fmaxf(tm1, __shfl_xor_sync(0xFFFFFFFF, tm1, 2));
        const float mn0 = fmaxf(m0, tm0);
        const float mn1 = fmaxf(m1, tm1);
        const float sc0 = __expf(m0 - mn0);
        const float sc1 = __expf(m1 - mn1);

        float ls0 = 0.f, ls1 = 0.f;
        #pragma unroll
        for (int nt = 0; nt < 8; nt++) {
            accs[nt][0] = __expf(accs[nt][0] - mn0);
            accs[nt][1] = __expf(accs[nt][1] - mn0);
            accs[nt][2] = __expf(accs[nt][2] - mn1);
            accs[nt][3] = __expf(accs[nt][3] - mn1);
            ls0 += accs[nt][0] + accs[nt][1];
            ls1 += accs[nt][2] + accs[nt][3];
        }
        ls0 += __shfl_xor_sync(0xFFFFFFFF, ls0, 1);
        ls0 += __shfl_xor_sync(0xFFFFFFFF, ls0, 2);
        ls1 += __shfl_xor_sync(0xFFFFFFFF, ls1, 1);
        ls1 += __shfl_xor_sync(0xFFFFFFFF, ls1, 2);
        l0 = l0 * sc0 + ls0;  m0 = mn0;
        l1 = l1 * sc1 + ls1;  m1 = mn1;

        #pragma unroll
        for (int dt = 0; dt < 16; dt++) {
            o[dt][0] *= sc0; o[dt][1] *= sc0;
            o[dt][2] *= sc1; o[dt][3] *= sc1;
        }

        #pragma unroll
        for (int ks = 0; ks < 4; ks++) {
            const int t0 = 2 * ks, t1 = 2 * ks + 1;
            uint32_t pha[4], pla[4];
            #pragma unroll
            for (int q = 0; q < 4; q++) {
                const float x0 = accs[(q & 2) ? t1 : t0][(q & 1) ? 2 : 0];
                const float x1 = accs[(q & 2) ? t1 : t0][(q & 1) ? 3 : 1];
                __nv_bfloat16 h0 = __float2bfloat16(x0);
                __nv_bfloat16 h1 = __float2bfloat16(x1);
                pha[q] = pack_bf2(h0, h1);
                pla[q] = pack_bf2(__float2bfloat16(x0 - __bfloat162float(h0)),
                                  __float2bfloat16(x1 - __bfloat162float(h1)));
            }
            #pragma unroll
            for (int dt = 0; dt < 16; dt++) {
                uint32_t vh[2], vl[2];
                const uint32_t va = (uint32_t)(ks * 16 + vrow) * ATT_STRIDE + dt * 16;
                ldmx2t(vh, Vhs + va);
                ldmx2t(vl, Vls + va);
                mma16816(o[dt], pha, vh);
                mma16816(o[dt], pha, vl);
                mma16816(o[dt], pla, vh);
            }
        }

        if (kt < qt) {
            __syncthreads();
            load_kv(kt + 1);
            asm volatile("cp.async.wait_group 0;");
            __syncthreads();
        }
    }

    // epilogue: normalize, write fp16 ctx
    const float inv0 = 1.f / l0;
    const float inv1 = 1.f / l1;
    const int tok0 = b * SEQ + qt * 64 + wid * 16 + (lane >> 2);
    const int tok1 = tok0 + 8;
    #pragma unroll
    for (int dt = 0; dt < 16; dt++) {
        const int col = h * DHEAD + dt * 8 + (lane & 3) * 2;
        __half2 w0 = __floats2half2_rn(o[dt][0] * inv0, o[dt][1] * inv0);
        __half2 w1 = __floats2half2_rn(o[dt][2] * inv1, o[dt][3] * inv1);
        *(uint32_t*)(g_ctx_h + (size_t)tok0 * HDIM + col) = *(uint32_t*)&w0;
        *(uint32_t*)(g_ctx_h + (size_t)tok1 * HDIM + col) = *(uint32_t*)&w1;
    }
}

// ---------------------------------------------------------------------------
// Launch
// ---------------------------------------------------------------------------
extern "C" void kernel_launch(void* const* d_in, const int* in_sizes, int n_in,
                              void* d_out, int out_size) {
    const int*   positions    = (const int*)  d_in[0];
    const float* hidden       = (const float*)d_in[1];
    const float* kv_cache_in  = (const float*)d_in[2];
    const int*   slot_mapping = (const int*)  d_in[4];
    const float* w_qkv = (const float*)d_in[n_in - 3];
    const float* b_qkv = (const float*)d_in[n_in - 2];
    const float* w_o   = (const float*)d_in[n_in - 1];

    float* out       = (float*)d_out;
    float* cache_out = out + (size_t)T_TOK * HDIM;

    float* qkv_ptr;
    __half *ctx_h, *hid_h, *wqkv_h, *wo_h;
    cudaGetSymbolAddress((void**)&qkv_ptr, g_qkv);
    cudaGetSymbolAddress((void**)&ctx_h,   g_ctx_h);
    cudaGetSymbolAddress((void**)&hid_h,   g_hid_h);
    cudaGetSymbolAddress((void**)&wqkv_h,  g_wqkv_h);
    cudaGetSymbolAddress((void**)&wo_h,    g_wo_h);

    cudaFuncSetAttribute(gemm_f16,
                         cudaFuncAttributeMaxDynamicSharedMemorySize, GSMEM_BYTES);
    cudaFuncSetAttribute(attn_mma,
                         cudaFuncAttributeMaxDynamicSharedMemorySize, ATT_SMEM);

    // 1) Seed output cache with the input cache
    cudaMemcpyAsync(cache_out, kv_cache_in,
                    (size_t)2 * NSLOTS * NKV * DHEAD * sizeof(float),
                    cudaMemcpyDeviceToDevice, 0);

    // 2) Convert hidden + w_qkv + w_o to fp16
    {
        int n4 = (T_TOK * HDIM) / 4;
        conv_f16<<<(n4 + 255) / 256, 256>>>((const float4*)hidden,
                                            (uint2*)hid_h, n4);
        n4 = (QKV_OUT * HDIM) / 4;
        conv_f16<<<(n4 + 255) / 256, 256>>>((const float4*)w_qkv,
                                            (uint2*)wqkv_h, n4);
        n4 = (HDIM * HDIM) / 4;
        conv_f16<<<(n4 + 255) / 256, 256>>>((const float4*)w_o,
                                            (uint2*)wo_h, n4);
    }

    // 3) QKV projection (fp16 tensor cores)
    {
        dim3 grid(QKV_OUT / 128, T_TOK / 128);
        gemm_f16<<<grid, 256, GSMEM_BYTES>>>(hid_h, wqkv_h, b_qkv, qkv_ptr,
                                             T_TOK, QKV_OUT, HDIM);
    }

    // 4) RoPE + cache scatter + bf16 mirrors
    rope_scatter_kernel<<<T_TOK, 128>>>(positions, slot_mapping, cache_out);

    // 5) Tensor-core flash attention -> fp16 ctx
    {
        dim3 grid(SEQ / 64, BATCH * NH);
        attn_mma<<<grid, 128, ATT_SMEM>>>(nullptr);
    }

    // 6) Output projection (fp16 tensor cores)
    {
        dim3 grid(HDIM / 128, T_TOK / 128);
        gemm_f16<<<grid, 256, GSMEM_BYTES>>>(ctx_h, wo_h, nullptr, out,
                                             T_TOK, HDIM, NH * DHEAD);
    }
}